// round 14
// baseline (speedup 1.0000x reference)
#include <cuda_runtime.h>
#include <cuda_fp16.h>

typedef unsigned int u32;

#define B_ 4
#define N_ 512
#define H_ 8
#define DH 16
#define DIM 128
#define M_ 8192
#define J_ 8704
#define BH 32
#define NTOK 2048
#define TJ 128
#define NSPLIT 4
#define NT4 17           // (J_/TJ)/NSPLIT
#define LOG2E 1.44269504f
#define NSHIFT (-8.65617025f)   /* = -6 * log2(e), fixed softmax shift */
#define BUFB 6144               /* bytes per K (or V) smem buffer: TJ*24*2 */

// ---- scratch (static device arrays: no allocation) ----
__device__ __align__(16) float  g_xs[NTOK * DIM];
__device__ __align__(16) float  g_qraw[NTOK * DIM];
__device__ __align__(16) __half g_qh[BH * N_ * DH];
__device__ __align__(16) float  g_cost[J_ * 8];
__device__ __align__(16) float  g_sint[J_ * 8];
__device__ __align__(16) __half g_kh[(size_t)BH * J_ * DH];  // rotated K, f16
__device__ __align__(16) __half g_vh[(size_t)BH * J_ * DH];  // V, f16
__device__ __align__(16) float  g_accP[(size_t)BH * NSPLIT * N_ * DH]; // partial numerators
__device__ __align__(16) float  g_lP[BH * NSPLIT * N_];               // partial denominators

__device__ __forceinline__ u32 smem_u32(const void* p) {
    u32 a;
    asm("{ .reg .u64 t; cvta.to.shared.u64 t, %1; cvt.u32.u64 %0, t; }"
        : "=r"(a) : "l"(p));
    return a;
}

// ---- K1: fused rotary tables + layernorm1 ----
__global__ void __launch_bounds__(256) k_init(const float* __restrict__ x,
                                              const float* __restrict__ g1,
                                              const float* __restrict__ b1) {
    int tid = threadIdx.x;
    if (blockIdx.x < 272) {
        int i = blockIdx.x * 256 + tid;
        int j = i >> 3, f = i & 7;
        float invf = exp2f((float)f * -1.66096404744f);  // 10000^(-f/8)
        float s, c;
        sincosf((float)j * invf, &s, &c);
        g_cost[i] = c;
        g_sint[i] = s;
        return;
    }
    int t = (blockIdx.x - 272) * 8 + (tid >> 5);
    int lane = tid & 31;
    const float* xr = x + (size_t)t * DIM;
    float v0 = xr[lane], v1 = xr[lane + 32], v2 = xr[lane + 64], v3 = xr[lane + 96];
    float sum = v0 + v1 + v2 + v3;
    float sq = v0 * v0 + v1 * v1 + v2 * v2 + v3 * v3;
    #pragma unroll
    for (int o = 16; o; o >>= 1) {
        sum += __shfl_xor_sync(~0u, sum, o);
        sq  += __shfl_xor_sync(~0u, sq, o);
    }
    float mu = sum * (1.0f / 128.0f);
    float var = sq * (1.0f / 128.0f) - mu * mu;
    float r = rsqrtf(var + 1e-5f);
    float* o = g_xs + (size_t)t * DIM;
    o[lane]      = (v0 - mu) * r * g1[lane]      + b1[lane];
    o[lane + 32] = (v1 - mu) * r * g1[lane + 32] + b1[lane + 32];
    o[lane + 64] = (v2 - mu) * r * g1[lane + 64] + b1[lane + 64];
    o[lane + 96] = (v3 - mu) * r * g1[lane + 96] + b1[lane + 96];
}

// ---- K2: Q / KV projections as blocked smem GEMM ----
__global__ void __launch_bounds__(256) k_proj(const float* __restrict__ wq,
                                              const float* __restrict__ wkv,
                                              float* __restrict__ memkv_out) {
    __shared__ float sw[128 * 68];
    __shared__ float sx[32 * 68];
    const int t0 = blockIdx.x * 32;
    const int ch = blockIdx.y;
    const float* wsrc = (ch == 0) ? wq : (wkv + (size_t)(ch - 1) * 128 * DIM);
    const int tid = threadIdx.x;
    const int og = tid & 31, tg = tid >> 5;

    float acc[4][4];
    #pragma unroll
    for (int t = 0; t < 4; t++)
        #pragma unroll
        for (int o = 0; o < 4; o++) acc[t][o] = 0.f;

    for (int kc = 0; kc < 2; kc++) {
        #pragma unroll
        for (int i = 0; i < 8; i++) {
            int idx = tid + i * 256;
            int o = idx >> 4, k4 = (idx & 15) * 4;
            *(float4*)&sw[o * 68 + k4] =
                *(const float4*)&wsrc[(size_t)o * DIM + kc * 64 + k4];
        }
        #pragma unroll
        for (int i = 0; i < 2; i++) {
            int idx = tid + i * 256;
            int t = idx >> 4, k4 = (idx & 15) * 4;
            *(float4*)&sx[t * 68 + k4] =
                *(const float4*)&g_xs[(size_t)(t0 + t) * DIM + kc * 64 + k4];
        }
        __syncthreads();
        const float* swb = sw + og * 68;
        const float* sxb = sx + tg * 4 * 68;
        #pragma unroll
        for (int ks = 0; ks < 16; ks++) {
            float4 w0 = *(const float4*)&swb[0 * 2176 + ks * 4];
            float4 w1 = *(const float4*)&swb[1 * 2176 + ks * 4];
            float4 w2 = *(const float4*)&swb[2 * 2176 + ks * 4];
            float4 w3 = *(const float4*)&swb[3 * 2176 + ks * 4];
            #pragma unroll
            for (int t = 0; t < 4; t++) {
                float4 xv = *(const float4*)&sxb[t * 68 + ks * 4];
                acc[t][0] += xv.x * w0.x + xv.y * w0.y + xv.z * w0.z + xv.w * w0.w;
                acc[t][1] += xv.x * w1.x + xv.y * w1.y + xv.z * w1.z + xv.w * w1.w;
                acc[t][2] += xv.x * w2.x + xv.y * w2.y + xv.z * w2.z + xv.w * w2.w;
                acc[t][3] += xv.x * w3.x + xv.y * w3.y + xv.z * w3.z + xv.w * w3.w;
            }
        }
        __syncthreads();
    }

    #pragma unroll
    for (int t = 0; t < 4; t++) {
        int gt = t0 + tg * 4 + t;
        if (ch == 0) {
            #pragma unroll
            for (int o = 0; o < 4; o++)
                g_qraw[(size_t)gt * DIM + og + 32 * o] = acc[t][o];
        } else {
            int b = gt >> 9, tt = gt & 511;
            #pragma unroll
            for (int o = 0; o < 4; o++) {
                int h = (ch - 1) * 4 + o;
                memkv_out[((size_t)(b * H_ + h) * J_ + (M_ + tt)) * 32 + og] = acc[t][o];
            }
        }
    }
}

// ---- helper: rotate+convert 32 staged KV rows from smem into g_kh/g_vh ----
__device__ __forceinline__ void rotconv_rows(const float* s, int r, int q, int j,
                                             size_t drow) {
    if (q < 4) {
        u32 out0, out1;
        #pragma unroll
        for (int i = 0; i < 2; i++) {
            int d0 = 4 * q + 2 * i, d1 = d0 + 1;
            float v0 = s[r * 36 + d0], p0 = s[r * 36 + (d0 ^ 8)];
            float v1 = s[r * 36 + d1], p1 = s[r * 36 + (d1 ^ 8)];
            float r0 = v0 * g_cost[j * 8 + (d0 & 7)] + ((d0 < 8) ? -p0 : p0) * g_sint[j * 8 + (d0 & 7)];
            float r1 = v1 * g_cost[j * 8 + (d1 & 7)] + ((d1 < 8) ? -p1 : p1) * g_sint[j * 8 + (d1 & 7)];
            u32 h2; asm("cvt.rn.f16x2.f32 %0, %1, %2;" : "=r"(h2) : "f"(r1), "f"(r0));
            if (i == 0) out0 = h2; else out1 = h2;
        }
        *(uint2*)((u32*)g_kh + drow * 8 + 2 * q) = make_uint2(out0, out1);
    } else {
        int qq = q - 4;
        u32 out0, out1;
        #pragma unroll
        for (int i = 0; i < 2; i++) {
            int d0 = 16 + 4 * qq + 2 * i;
            u32 h2; asm("cvt.rn.f16x2.f32 %0, %1, %2;"
                        : "=r"(h2) : "f"(s[r * 36 + d0 + 1]), "f"(s[r * 36 + d0]));
            if (i == 0) out0 = h2; else out1 = h2;
        }
        *(uint2*)((u32*)g_vh + drow * 8 + 2 * qq) = make_uint2(out0, out1);
    }
}

// ---- K3 (fused): prep (old cache) + newkv + qrot ----
__global__ void __launch_bounds__(256) k_mid(const float4* __restrict__ src,
                                             float4* __restrict__ dst) {
    int blk = blockIdx.x;
    int tid = threadIdx.x;
    if (blk < 8192) {
        __shared__ float s[32 * 36];
        int bh = blk >> 8;
        int j0 = (blk & 255) << 5;
        int r = tid >> 3, c = tid & 7;
        size_t srow = (size_t)bh * M_ + j0 + r;
        size_t drow = (size_t)bh * J_ + j0 + r;
        float4 v = src[srow * 8 + c];
        dst[drow * 8 + c] = v;
        *(float4*)(s + r * 36 + c * 4) = v;
        __syncthreads();
        rotconv_rows(s, r, tid & 7, j0 + r, drow);
        return;
    }
    if (blk < 8704) {
        __shared__ float s2[32 * 36];
        int b2 = blk - 8192;
        int bh = b2 >> 4;
        int j0 = M_ + ((b2 & 15) << 5);
        int r = tid >> 3, c = tid & 7;
        size_t drow = (size_t)bh * J_ + j0 + r;
        float4 v = dst[drow * 8 + c];
        *(float4*)(s2 + r * 36 + c * 4) = v;
        __syncthreads();
        rotconv_rows(s2, r, tid & 7, j0 + r, drow);
        return;
    }
    int i = (blk - 8704) * 256 + tid;      // < NTOK*DIM
    int d = i & 127, gt = i >> 7;
    int dd = d & 15, hh = d >> 4;
    int b = gt >> 9, tt = gt & 511;
    int f = dd & 7;
    int pos = M_ + tt;
    float c = g_cost[pos * 8 + f];
    float s = g_sint[pos * 8 + f];
    float v = g_qraw[i];
    float vp = g_qraw[((size_t)gt << 7) + (hh << 4) + (dd ^ 8)];
    float rh = (dd < 8) ? -vp : vp;
    float q = (v * c + rh * s) * (0.25f * LOG2E);
    g_qh[((size_t)(b * H_ + hh) * N_ + tt) * DH + dd] = __float2half(q);
}

// ---- K4: attention, m64 Q-tile per warp (4 fragment chains share each K/V
//      ldmatrix), 4 warps/CTA (256 q rows), NSPLIT=4 -> 256 CTAs; triple-buffer ----
__global__ void __launch_bounds__(128, 3) k_attn() {
    __shared__ __half sK[3][TJ * 24];   // K tiles, 48B row stride
    __shared__ __half sV[3][TJ * 24];   // V tiles, 48B row stride
    const int bh = blockIdx.x, qt = blockIdx.y, sp = blockIdx.z;
    const int tid = threadIdx.x, wid = tid >> 5, lane = tid & 31;
    const int g = lane >> 2, w = lane & 3;

    // four resident Q A-fragments: rows qt*256 + wid*64 + 16*f + {g, g+8}
    const __half* qb = g_qh + ((size_t)(bh * N_ + qt * 256 + wid * 64)) * DH;
    u32 qf[4][4];
    #pragma unroll
    for (int f = 0; f < 4; f++) {
        const __half* qq = qb + (size_t)(16 * f) * DH;
        qf[f][0] = *(const u32*)(qq + (size_t)g * DH + 2 * w);
        qf[f][1] = *(const u32*)(qq + (size_t)(g + 8) * DH + 2 * w);
        qf[f][2] = *(const u32*)(qq + (size_t)g * DH + 2 * w + 8);
        qf[f][3] = *(const u32*)(qq + (size_t)(g + 8) * DH + 2 * w + 8);
    }

    float oacc[4][8];
    float lf[4][2];
    #pragma unroll
    for (int f = 0; f < 4; f++) {
        #pragma unroll
        for (int i = 0; i < 8; i++) oacc[f][i] = 0.f;
        lf[f][0] = 0.f; lf[f][1] = 0.f;
    }

    const __half hns = __float2half(NSHIFT);
    const u32 ns2 = ((u32)__half_as_ushort(hns) << 16) | __half_as_ushort(hns);

    // staging: thread -> key row tid (32B K row + 32B V row via 2+2 cp.async)
    const int ki = tid;
    const int jbase = sp * NT4 * TJ;
    const u32* kg = (const u32*)g_kh + (size_t)bh * J_ * 8;
    const u32* vg = (const u32*)g_vh + (size_t)bh * J_ * 8;

    const u32 sKa = smem_u32(sK), sVa = smem_u32(sV);
    const u32 kdst = sKa + (u32)(ki * 48);
    const u32 vdst = sVa + (u32)(ki * 48);

    // ldmatrix lane addresses (buffer 0 base)
    const int r8 = lane & 7, m4 = lane >> 3;
    const u32 kaddr0 = sKa + (u32)((((m4 >> 1) * 8 + r8) * 48) + (m4 & 1) * 16);
    const u32 vaddr0 = sVa + (u32)((((m4 & 1) * 8 + r8) * 48) + (m4 >> 1) * 16);

    #define ISSUE(buf, tile) do {                                                   \
        size_t jrow = (size_t)(jbase + (tile) * TJ + ki) * 8;                        \
        asm volatile("cp.async.ca.shared.global [%0], [%1], 16;"                    \
                     :: "r"(kdst + (buf) * BUFB), "l"(kg + jrow));                   \
        asm volatile("cp.async.ca.shared.global [%0], [%1], 16;"                    \
                     :: "r"(kdst + (buf) * BUFB + 16), "l"(kg + jrow + 4));          \
        asm volatile("cp.async.ca.shared.global [%0], [%1], 16;"                    \
                     :: "r"(vdst + (buf) * BUFB), "l"(vg + jrow));                   \
        asm volatile("cp.async.ca.shared.global [%0], [%1], 16;"                    \
                     :: "r"(vdst + (buf) * BUFB + 16), "l"(vg + jrow + 4));          \
        asm volatile("cp.async.commit_group;");                                     \
    } while (0)

    ISSUE(0, 0);
    ISSUE(1, 1);

    int bufc = 0;
    for (int t = 0; t < NT4; t++) {
        if (t + 1 < NT4) {
            asm volatile("cp.async.wait_group 1;");
        } else {
            asm volatile("cp.async.wait_group 0;");
        }
        __syncthreads();   // tile t visible; all warps done with tile t-1
        if (t + 2 < NT4) {
            int bslot = bufc + 2; if (bslot >= 3) bslot -= 3;
            ISSUE(bslot, t + 2);
        }

        const u32 kB = kaddr0 + bufc * BUFB;
        const u32 vB = vaddr0 + bufc * BUFB;
        #pragma unroll
        for (int kc = 0; kc < 8; kc++) {
            u32 kb0, kb1, kb2, kb3;
            asm volatile("ldmatrix.sync.aligned.m8n8.x4.shared.b16 {%0,%1,%2,%3}, [%4];"
                : "=r"(kb0), "=r"(kb1), "=r"(kb2), "=r"(kb3) : "r"(kB + kc * 768));
            u32 p[4][4];
            #pragma unroll
            for (int f = 0; f < 4; f++) {
                asm volatile("mma.sync.aligned.m16n8k16.row.col.f16.f16.f16.f16 "
                    "{%0,%1}, {%2,%3,%4,%5}, {%6,%7}, {%8,%9};"
                    : "=r"(p[f][0]), "=r"(p[f][1])
                    : "r"(qf[f][0]), "r"(qf[f][1]), "r"(qf[f][2]), "r"(qf[f][3]),
                      "r"(kb0), "r"(kb1), "r"(ns2), "r"(ns2));
                asm volatile("mma.sync.aligned.m16n8k16.row.col.f16.f16.f16.f16 "
                    "{%0,%1}, {%2,%3,%4,%5}, {%6,%7}, {%8,%9};"
                    : "=r"(p[f][2]), "=r"(p[f][3])
                    : "r"(qf[f][0]), "r"(qf[f][1]), "r"(qf[f][2]), "r"(qf[f][3]),
                      "r"(kb2), "r"(kb3), "r"(ns2), "r"(ns2));
            }
            #pragma unroll
            for (int f = 0; f < 4; f++) {
                asm("ex2.approx.f16x2 %0, %0;" : "+r"(p[f][0]));
                asm("ex2.approx.f16x2 %0, %0;" : "+r"(p[f][1]));
                asm("ex2.approx.f16x2 %0, %0;" : "+r"(p[f][2]));
                asm("ex2.approx.f16x2 %0, %0;" : "+r"(p[f][3]));
            }
            #pragma unroll
            for (int f = 0; f < 4; f++) {
                __half2 t0 = __hadd2(*(__half2*)&p[f][0], *(__half2*)&p[f][2]);
                __half2 t1 = __hadd2(*(__half2*)&p[f][1], *(__half2*)&p[f][3]);
                float2 f0 = __half22float2(t0);
                float2 f1 = __half22float2(t1);
                lf[f][0] += f0.x + f0.y;
                lf[f][1] += f1.x + f1.y;
            }
            u32 v0, v1, v2, v3;
            asm volatile("ldmatrix.sync.aligned.m8n8.x4.trans.shared.b16 {%0,%1,%2,%3}, [%4];"
                : "=r"(v0), "=r"(v1), "=r"(v2), "=r"(v3) : "r"(vB + kc * 768));
            #pragma unroll
            for (int f = 0; f < 4; f++) {
                asm volatile("mma.sync.aligned.m16n8k16.row.col.f32.f16.f16.f32 "
                    "{%0,%1,%2,%3}, {%4,%5,%6,%7}, {%8,%9}, {%0,%1,%2,%3};"
                    : "+f"(oacc[f][0]), "+f"(oacc[f][1]), "+f"(oacc[f][2]), "+f"(oacc[f][3])
                    : "r"(p[f][0]), "r"(p[f][1]), "r"(p[f][2]), "r"(p[f][3]),
                      "r"(v0), "r"(v1));
                asm volatile("mma.sync.aligned.m16n8k16.row.col.f32.f16.f16.f32 "
                    "{%0,%1,%2,%3}, {%4,%5,%6,%7}, {%8,%9}, {%0,%1,%2,%3};"
                    : "+f"(oacc[f][4]), "+f"(oacc[f][5]), "+f"(oacc[f][6]), "+f"(oacc[f][7])
                    : "r"(p[f][0]), "r"(p[f][1]), "r"(p[f][2]), "r"(p[f][3]),
                      "r"(v2), "r"(v3));
            }
        }
        bufc = (bufc + 1 == 3) ? 0 : bufc + 1;
    }
    #undef ISSUE

    // reduce l across the quad (keys partitioned over w=0..3)
    #pragma unroll
    for (int f = 0; f < 4; f++) {
        lf[f][0] += __shfl_xor_sync(0xffffffffu, lf[f][0], 1);
        lf[f][0] += __shfl_xor_sync(0xffffffffu, lf[f][0], 2);
        lf[f][1] += __shfl_xor_sync(0xffffffffu, lf[f][1], 1);
        lf[f][1] += __shfl_xor_sync(0xffffffffu, lf[f][1], 2);
    }

    int row0 = qt * 256 + wid * 64 + g;
    size_t lb = (size_t)(bh * NSPLIT + sp) * N_ + row0;
    #pragma unroll
    for (int f = 0; f < 4; f++) {
        size_t pb = (lb + 16 * f) * DH;
        float* o0 = g_accP + pb;
        float* o1 = g_accP + pb + (size_t)8 * DH;
        o0[2 * w]     = oacc[f][0]; o0[2 * w + 1]     = oacc[f][1];
        o0[8 + 2 * w] = oacc[f][4]; o0[8 + 2 * w + 1] = oacc[f][5];
        o1[2 * w]     = oacc[f][2]; o1[2 * w + 1]     = oacc[f][3];
        o1[8 + 2 * w] = oacc[f][6]; o1[8 + 2 * w + 1] = oacc[f][7];
        if (w == 0) {
            g_lP[lb + 16 * f]     = lf[f][0];
            g_lP[lb + 16 * f + 8] = lf[f][1];
        }
    }
}

// ---- K5: combine splits + residual + LN2 + out proj + residual ----
__global__ void k_epi(const float* __restrict__ x, const float* __restrict__ wout,
                      const float* __restrict__ bout, const float* __restrict__ g2,
                      const float* __restrict__ b2, float* __restrict__ out) {
    __shared__ float shv[8 * DIM];
    __shared__ float sy[8 * DIM];
    int tok0 = blockIdx.x * 8;
    int tid = threadIdx.x;
    for (int i = tid; i < 8 * DIM; i += 256) {
        int gt = tok0 + (i >> 7);
        int d = i & 127;
        int b = gt >> 9, t = gt & 511;
        int bh = b * H_ + (d >> 4);
        int dd = d & 15;
        float num = 0.f, l = 0.f;
        #pragma unroll
        for (int s = 0; s < NSPLIT; s++) {
            num += g_accP[((size_t)(bh * NSPLIT + s) * N_ + t) * DH + dd];
            l   += g_lP[(size_t)(bh * NSPLIT + s) * N_ + t];
        }
        shv[i] = __fdividef(num, l) + x[(size_t)gt * DIM + d];
    }
    __syncthreads();
    int w = tid >> 5, lane = tid & 31;
    float v0 = shv[w * DIM + lane], v1 = shv[w * DIM + lane + 32];
    float v2 = shv[w * DIM + lane + 64], v3 = shv[w * DIM + lane + 96];
    float sum = v0 + v1 + v2 + v3;
    float sq = v0 * v0 + v1 * v1 + v2 * v2 + v3 * v3;
    #pragma unroll
    for (int o = 16; o; o >>= 1) {
        sum += __shfl_xor_sync(~0u, sum, o);
        sq  += __shfl_xor_sync(~0u, sq, o);
    }
    float mu = sum * (1.0f / 128.0f);
    float var = sq * (1.0f / 128.0f) - mu * mu;
    float r = rsqrtf(var + 1e-5f);
    sy[w * DIM + lane]      = (v0 - mu) * r * g2[lane]      + b2[lane];
    sy[w * DIM + lane + 32] = (v1 - mu) * r * g2[lane + 32] + b2[lane + 32];
    sy[w * DIM + lane + 64] = (v2 - mu) * r * g2[lane + 64] + b2[lane + 64];
    sy[w * DIM + lane + 96] = (v3 - mu) * r * g2[lane + 96] + b2[lane + 96];
    __syncthreads();
    int o = tid & 127, grp = tid >> 7;
    const float* wrow = wout + (size_t)o * DIM;
    int t0 = grp * 4;
    float a0 = 0.f, a1 = 0.f, a2 = 0.f, a3 = 0.f;
    for (int d = 0; d < DIM; d++) {
        float wv = wrow[d];
        a0 = fmaf(wv, sy[(t0 + 0) * DIM + d], a0);
        a1 = fmaf(wv, sy[(t0 + 1) * DIM + d], a1);
        a2 = fmaf(wv, sy[(t0 + 2) * DIM + d], a2);
        a3 = fmaf(wv, sy[(t0 + 3) * DIM + d], a3);
    }
    float bo = bout[o];
    out[(size_t)(tok0 + t0 + 0) * DIM + o] = a0 + bo + shv[(t0 + 0) * DIM + o];
    out[(size_t)(tok0 + t0 + 1) * DIM + o] = a1 + bo + shv[(t0 + 1) * DIM + o];
    out[(size_t)(tok0 + t0 + 2) * DIM + o] = a2 + bo + shv[(t0 + 2) * DIM + o];
    out[(size_t)(tok0 + t0 + 3) * DIM + o] = a3 + bo + shv[(t0 + 3) * DIM + o];
}

extern "C" void kernel_launch(void* const* d_in, const int* in_sizes, int n_in,
                              void* d_out, int out_size) {
    const float* x      = (const float*)d_in[0];
    const float* mem_kv = (const float*)d_in[1];
    const float* w_q    = (const float*)d_in[2];
    const float* w_kv   = (const float*)d_in[3];
    const float* w_out  = (const float*)d_in[4];
    const float* b_out  = (const float*)d_in[5];
    const float* g1     = (const float*)d_in[6];
    const float* b1     = (const float*)d_in[7];
    const float* g2     = (const float*)d_in[8];
    const float* b2     = (const float*)d_in[9];

    float* out = (float*)d_out;                  // [4,512,128]
    float* memkv_out = out + (size_t)NTOK * DIM; // [4,8,8704,32]

    k_init<<<528, 256>>>(x, g1, b1);
    k_proj<<<dim3(64, 3), 256>>>(w_q, w_kv, memkv_out);
    k_mid<<<9728, 256>>>((const float4*)mem_kv, (float4*)memkv_out);
    k_attn<<<dim3(BH, 2, NSPLIT), 128>>>();
    k_epi<<<NTOK / 8, 256>>>(x, w_out, b_out, g2, b2, out);
}

// round 15
// speedup vs baseline: 1.0609x; 1.0609x over previous
#include <cuda_runtime.h>
#include <cuda_fp16.h>

typedef unsigned int u32;

#define B_ 4
#define N_ 512
#define H_ 8
#define DH 16
#define DIM 128
#define M_ 8192
#define J_ 8704
#define BH 32
#define NTOK 2048
#define TJ 128
#define NSPLIT 4
#define NT4 17           // (J_/TJ)/NSPLIT
#define LOG2E 1.44269504f
#define NSHIFT (-8.65617025f)   /* = -6 * log2(e), fixed softmax shift */
#define BUFB 6144               /* bytes per K (or V) smem buffer: TJ*24*2 */

// ---- scratch (static device arrays: no allocation) ----
__device__ __align__(16) float  g_qraw[NTOK * DIM];
__device__ __align__(16) __half g_qh[BH * N_ * DH];
__device__ __align__(16) float  g_cost[J_ * 8];
__device__ __align__(16) float  g_sint[J_ * 8];
__device__ __align__(16) __half g_kh[(size_t)BH * J_ * DH];  // rotated K, f16
__device__ __align__(16) __half g_vh[(size_t)BH * J_ * DH];  // V, f16
__device__ __align__(16) float  g_accP[(size_t)BH * NSPLIT * N_ * DH]; // partial numerators
__device__ __align__(16) float  g_lP[BH * NSPLIT * N_];               // partial denominators

__device__ __forceinline__ u32 smem_u32(const void* p) {
    u32 a;
    asm("{ .reg .u64 t; cvta.to.shared.u64 t, %1; cvt.u32.u64 %0, t; }"
        : "=r"(a) : "l"(p));
    return a;
}

// ---- K1 (fused head): rotary tables (blocks 192..463) +
//      LN1-inline Q/KV projection GEMM (blocks 0..191) ----
__global__ void __launch_bounds__(256) k_head(const float* __restrict__ x,
                                              const float* __restrict__ g1,
                                              const float* __restrict__ b1,
                                              const float* __restrict__ wq,
                                              const float* __restrict__ wkv,
                                              float* __restrict__ memkv_out) {
    __shared__ float sw[128 * 68];   // weight tile [128 out][64 k], stride 68
    __shared__ float sx[32 * 68];    // normalized x tile [32 tok][64 k]
    __shared__ float smu[32], srv[32];
    const int tid = threadIdx.x;

    if (blockIdx.x >= 192) {
        // rotary tables: 272 blocks * 256 = J_*8 exactly
        int i = (blockIdx.x - 192) * 256 + tid;
        int j = i >> 3, f = i & 7;
        float invf = exp2f((float)f * -1.66096404744f);  // 10000^(-f/8)
        float s, c;
        sincosf((float)j * invf, &s, &c);
        g_cost[i] = c;
        g_sint[i] = s;
        return;
    }

    const int pb = blockIdx.x;
    const int t0 = (pb & 63) * 32;
    const int ch = pb >> 6;
    const float* wsrc = (ch == 0) ? wq : (wkv + (size_t)(ch - 1) * 128 * DIM);
    const int og = tid & 31, tg = tid >> 5;

    // LN stats: 8 lanes per token (tok = tid>>3, sub = tid&7), groups
    // aligned within warps so shfl_xor 1/2/4 stays in-group.
    {
        int tok = tid >> 3, sub = tid & 7;
        const float* xr = x + (size_t)(t0 + tok) * DIM + sub * 16;
        float sum = 0.f, sq = 0.f;
        #pragma unroll
        for (int i = 0; i < 4; i++) {
            float4 v = *(const float4*)(xr + i * 4);
            sum += v.x + v.y + v.z + v.w;
            sq  += v.x * v.x + v.y * v.y + v.z * v.z + v.w * v.w;
        }
        #pragma unroll
        for (int o = 4; o; o >>= 1) {
            sum += __shfl_xor_sync(~0u, sum, o);
            sq  += __shfl_xor_sync(~0u, sq, o);
        }
        float mu = sum * (1.0f / 128.0f);
        float var = sq * (1.0f / 128.0f) - mu * mu;
        if (sub == 0) { smu[tok] = mu; srv[tok] = rsqrtf(var + 1e-5f); }
    }
    __syncthreads();

    float acc[4][4];
    #pragma unroll
    for (int t = 0; t < 4; t++)
        #pragma unroll
        for (int o = 0; o < 4; o++) acc[t][o] = 0.f;

    for (int kc = 0; kc < 2; kc++) {
        #pragma unroll
        for (int i = 0; i < 8; i++) {
            int idx = tid + i * 256;
            int o = idx >> 4, k4 = (idx & 15) * 4;
            *(float4*)&sw[o * 68 + k4] =
                *(const float4*)&wsrc[(size_t)o * DIM + kc * 64 + k4];
        }
        // stage x with LN applied on the fly
        #pragma unroll
        for (int i = 0; i < 2; i++) {
            int idx = tid + i * 256;
            int t = idx >> 4, k4 = (idx & 15) * 4;
            float4 raw = *(const float4*)&x[(size_t)(t0 + t) * DIM + kc * 64 + k4];
            float4 gg = *(const float4*)&g1[kc * 64 + k4];
            float4 bb = *(const float4*)&b1[kc * 64 + k4];
            float mu = smu[t], rv = srv[t];
            float4 nn;
            nn.x = (raw.x - mu) * rv * gg.x + bb.x;
            nn.y = (raw.y - mu) * rv * gg.y + bb.y;
            nn.z = (raw.z - mu) * rv * gg.z + bb.z;
            nn.w = (raw.w - mu) * rv * gg.w + bb.w;
            *(float4*)&sx[t * 68 + k4] = nn;
        }
        __syncthreads();
        const float* swb = sw + og * 68;
        const float* sxb = sx + tg * 4 * 68;
        #pragma unroll
        for (int ks = 0; ks < 16; ks++) {
            float4 w0 = *(const float4*)&swb[0 * 2176 + ks * 4];
            float4 w1 = *(const float4*)&swb[1 * 2176 + ks * 4];
            float4 w2 = *(const float4*)&swb[2 * 2176 + ks * 4];
            float4 w3 = *(const float4*)&swb[3 * 2176 + ks * 4];
            #pragma unroll
            for (int t = 0; t < 4; t++) {
                float4 xv = *(const float4*)&sxb[t * 68 + ks * 4];
                acc[t][0] += xv.x * w0.x + xv.y * w0.y + xv.z * w0.z + xv.w * w0.w;
                acc[t][1] += xv.x * w1.x + xv.y * w1.y + xv.z * w1.z + xv.w * w1.w;
                acc[t][2] += xv.x * w2.x + xv.y * w2.y + xv.z * w2.z + xv.w * w2.w;
                acc[t][3] += xv.x * w3.x + xv.y * w3.y + xv.z * w3.z + xv.w * w3.w;
            }
        }
        __syncthreads();
    }

    #pragma unroll
    for (int t = 0; t < 4; t++) {
        int gt = t0 + tg * 4 + t;
        if (ch == 0) {
            #pragma unroll
            for (int o = 0; o < 4; o++)
                g_qraw[(size_t)gt * DIM + og + 32 * o] = acc[t][o];
        } else {
            int b = gt >> 9, tt = gt & 511;
            #pragma unroll
            for (int o = 0; o < 4; o++) {
                int h = (ch - 1) * 4 + o;
                memkv_out[((size_t)(b * H_ + h) * J_ + (M_ + tt)) * 32 + og] = acc[t][o];
            }
        }
    }
}

// ---- helper: rotate+convert 32 staged KV rows from smem into g_kh/g_vh ----
__device__ __forceinline__ void rotconv_rows(const float* s, int r, int q, int j,
                                             size_t drow) {
    if (q < 4) {
        u32 out0, out1;
        #pragma unroll
        for (int i = 0; i < 2; i++) {
            int d0 = 4 * q + 2 * i, d1 = d0 + 1;
            float v0 = s[r * 36 + d0], p0 = s[r * 36 + (d0 ^ 8)];
            float v1 = s[r * 36 + d1], p1 = s[r * 36 + (d1 ^ 8)];
            float r0 = v0 * g_cost[j * 8 + (d0 & 7)] + ((d0 < 8) ? -p0 : p0) * g_sint[j * 8 + (d0 & 7)];
            float r1 = v1 * g_cost[j * 8 + (d1 & 7)] + ((d1 < 8) ? -p1 : p1) * g_sint[j * 8 + (d1 & 7)];
            u32 h2; asm("cvt.rn.f16x2.f32 %0, %1, %2;" : "=r"(h2) : "f"(r1), "f"(r0));
            if (i == 0) out0 = h2; else out1 = h2;
        }
        *(uint2*)((u32*)g_kh + drow * 8 + 2 * q) = make_uint2(out0, out1);
    } else {
        int qq = q - 4;
        u32 out0, out1;
        #pragma unroll
        for (int i = 0; i < 2; i++) {
            int d0 = 16 + 4 * qq + 2 * i;
            u32 h2; asm("cvt.rn.f16x2.f32 %0, %1, %2;"
                        : "=r"(h2) : "f"(s[r * 36 + d0 + 1]), "f"(s[r * 36 + d0]));
            if (i == 0) out0 = h2; else out1 = h2;
        }
        *(uint2*)((u32*)g_vh + drow * 8 + 2 * qq) = make_uint2(out0, out1);
    }
}

// ---- K2 (fused): prep (old cache) + newkv + qrot ----
__global__ void __launch_bounds__(256) k_mid(const float4* __restrict__ src,
                                             float4* __restrict__ dst) {
    int blk = blockIdx.x;
    int tid = threadIdx.x;
    if (blk < 8192) {
        __shared__ float s[32 * 36];
        int bh = blk >> 8;
        int j0 = (blk & 255) << 5;
        int r = tid >> 3, c = tid & 7;
        size_t srow = (size_t)bh * M_ + j0 + r;
        size_t drow = (size_t)bh * J_ + j0 + r;
        float4 v = src[srow * 8 + c];
        dst[drow * 8 + c] = v;
        *(float4*)(s + r * 36 + c * 4) = v;
        __syncthreads();
        rotconv_rows(s, r, tid & 7, j0 + r, drow);
        return;
    }
    if (blk < 8704) {
        __shared__ float s2[32 * 36];
        int b2 = blk - 8192;
        int bh = b2 >> 4;
        int j0 = M_ + ((b2 & 15) << 5);
        int r = tid >> 3, c = tid & 7;
        size_t drow = (size_t)bh * J_ + j0 + r;
        float4 v = dst[drow * 8 + c];
        *(float4*)(s2 + r * 36 + c * 4) = v;
        __syncthreads();
        rotconv_rows(s2, r, tid & 7, j0 + r, drow);
        return;
    }
    int i = (blk - 8704) * 256 + tid;      // < NTOK*DIM
    int d = i & 127, gt = i >> 7;
    int dd = d & 15, hh = d >> 4;
    int b = gt >> 9, tt = gt & 511;
    int f = dd & 7;
    int pos = M_ + tt;
    float c = g_cost[pos * 8 + f];
    float s = g_sint[pos * 8 + f];
    float v = g_qraw[i];
    float vp = g_qraw[((size_t)gt << 7) + (hh << 4) + (dd ^ 8)];
    float rh = (dd < 8) ? -vp : vp;
    float q = (v * c + rh * s) * (0.25f * LOG2E);
    g_qh[((size_t)(b * H_ + hh) * N_ + tt) * DH + dd] = __float2half(q);
}

// ---- K3: attention, m32 Q-tile per warp (R13 config: best known),
//      4 warps/CTA, NSPLIT=4 -> 512 CTAs; triple-buffered cp.async ----
__global__ void __launch_bounds__(128, 4) k_attn() {
    __shared__ __half sK[3][TJ * 24];   // K tiles, 48B row stride
    __shared__ __half sV[3][TJ * 24];   // V tiles, 48B row stride
    const int bh = blockIdx.x, qt = blockIdx.y, sp = blockIdx.z;
    const int tid = threadIdx.x, wid = tid >> 5, lane = tid & 31;
    const int g = lane >> 2, w = lane & 3;

    // two resident Q A-fragments: rows qt*128 + wid*32 + {g,g+8} and +16
    const __half* qp = g_qh + ((size_t)(bh * N_ + qt * TJ + wid * 32)) * DH;
    u32 qa0 = *(const u32*)(qp + (size_t)g * DH + 2 * w);
    u32 qa1 = *(const u32*)(qp + (size_t)(g + 8) * DH + 2 * w);
    u32 qa2 = *(const u32*)(qp + (size_t)g * DH + 2 * w + 8);
    u32 qa3 = *(const u32*)(qp + (size_t)(g + 8) * DH + 2 * w + 8);
    const __half* qp2 = qp + (size_t)16 * DH;
    u32 qb0 = *(const u32*)(qp2 + (size_t)g * DH + 2 * w);
    u32 qb1 = *(const u32*)(qp2 + (size_t)(g + 8) * DH + 2 * w);
    u32 qb2 = *(const u32*)(qp2 + (size_t)g * DH + 2 * w + 8);
    u32 qb3 = *(const u32*)(qp2 + (size_t)(g + 8) * DH + 2 * w + 8);

    float oA[8], oB[8];
    #pragma unroll
    for (int i = 0; i < 8; i++) { oA[i] = 0.f; oB[i] = 0.f; }
    float l0 = 0.f, l1 = 0.f, l2 = 0.f, l3 = 0.f;

    const __half hns = __float2half(NSHIFT);
    const u32 ns2 = ((u32)__half_as_ushort(hns) << 16) | __half_as_ushort(hns);

    // staging: thread -> key row tid (32B K row + 32B V row via 2+2 cp.async)
    const int ki = tid;
    const int jbase = sp * NT4 * TJ;
    const u32* kg = (const u32*)g_kh + (size_t)bh * J_ * 8;
    const u32* vg = (const u32*)g_vh + (size_t)bh * J_ * 8;

    const u32 sKa = smem_u32(sK), sVa = smem_u32(sV);
    const u32 kdst = sKa + (u32)(ki * 48);
    const u32 vdst = sVa + (u32)(ki * 48);

    // ldmatrix lane addresses (buffer 0 base)
    const int r8 = lane & 7, m4 = lane >> 3;
    const u32 kaddr0 = sKa + (u32)((((m4 >> 1) * 8 + r8) * 48) + (m4 & 1) * 16);
    const u32 vaddr0 = sVa + (u32)((((m4 & 1) * 8 + r8) * 48) + (m4 >> 1) * 16);

    #define ISSUE(buf, tile) do {                                                   \
        size_t jrow = (size_t)(jbase + (tile) * TJ + ki) * 8;                        \
        asm volatile("cp.async.ca.shared.global [%0], [%1], 16;"                    \
                     :: "r"(kdst + (buf) * BUFB), "l"(kg + jrow));                   \
        asm volatile("cp.async.ca.shared.global [%0], [%1], 16;"                    \
                     :: "r"(kdst + (buf) * BUFB + 16), "l"(kg + jrow + 4));          \
        asm volatile("cp.async.ca.shared.global [%0], [%1], 16;"                    \
                     :: "r"(vdst + (buf) * BUFB), "l"(vg + jrow));                   \
        asm volatile("cp.async.ca.shared.global [%0], [%1], 16;"                    \
                     :: "r"(vdst + (buf) * BUFB + 16), "l"(vg + jrow + 4));          \
        asm volatile("cp.async.commit_group;");                                     \
    } while (0)

    ISSUE(0, 0);
    ISSUE(1, 1);

    int bufc = 0;
    for (int t = 0; t < NT4; t++) {
        if (t + 1 < NT4) {
            asm volatile("cp.async.wait_group 1;");
        } else {
            asm volatile("cp.async.wait_group 0;");
        }
        __syncthreads();   // tile t visible; all warps done with tile t-1
        if (t + 2 < NT4) {
            int bslot = bufc + 2; if (bslot >= 3) bslot -= 3;
            ISSUE(bslot, t + 2);
        }

        const u32 kB = kaddr0 + bufc * BUFB;
        const u32 vB = vaddr0 + bufc * BUFB;
        #pragma unroll
        for (int kc = 0; kc < 8; kc++) {
            u32 kb0, kb1, kb2, kb3;
            asm volatile("ldmatrix.sync.aligned.m8n8.x4.shared.b16 {%0,%1,%2,%3}, [%4];"
                : "=r"(kb0), "=r"(kb1), "=r"(kb2), "=r"(kb3) : "r"(kB + kc * 768));
            u32 pA0, pA1, pA2, pA3, pB0, pB1, pB2, pB3;
            asm volatile("mma.sync.aligned.m16n8k16.row.col.f16.f16.f16.f16 "
                "{%0,%1}, {%2,%3,%4,%5}, {%6,%7}, {%8,%9};"
                : "=r"(pA0), "=r"(pA1)
                : "r"(qa0), "r"(qa1), "r"(qa2), "r"(qa3), "r"(kb0), "r"(kb1),
                  "r"(ns2), "r"(ns2));
            asm volatile("mma.sync.aligned.m16n8k16.row.col.f16.f16.f16.f16 "
                "{%0,%1}, {%2,%3,%4,%5}, {%6,%7}, {%8,%9};"
                : "=r"(pA2), "=r"(pA3)
                : "r"(qa0), "r"(qa1), "r"(qa2), "r"(qa3), "r"(kb2), "r"(kb3),
                  "r"(ns2), "r"(ns2));
            asm volatile("mma.sync.aligned.m16n8k16.row.col.f16.f16.f16.f16 "
                "{%0,%1}, {%2,%3,%4,%5}, {%6,%7}, {%8,%9};"
                : "=r"(pB0), "=r"(pB1)
                : "r"(qb0), "r"(qb1), "r"(qb2), "r"(qb3), "r"(kb0), "r"(kb1),
                  "r"(ns2), "r"(ns2));
            asm volatile("mma.sync.aligned.m16n8k16.row.col.f16.f16.f16.f16 "
                "{%0,%1}, {%2,%3,%4,%5}, {%6,%7}, {%8,%9};"
                : "=r"(pB2), "=r"(pB3)
                : "r"(qb0), "r"(qb1), "r"(qb2), "r"(qb3), "r"(kb2), "r"(kb3),
                  "r"(ns2), "r"(ns2));
            asm("ex2.approx.f16x2 %0, %0;" : "+r"(pA0));
            asm("ex2.approx.f16x2 %0, %0;" : "+r"(pA1));
            asm("ex2.approx.f16x2 %0, %0;" : "+r"(pA2));
            asm("ex2.approx.f16x2 %0, %0;" : "+r"(pA3));
            asm("ex2.approx.f16x2 %0, %0;" : "+r"(pB0));
            asm("ex2.approx.f16x2 %0, %0;" : "+r"(pB1));
            asm("ex2.approx.f16x2 %0, %0;" : "+r"(pB2));
            asm("ex2.approx.f16x2 %0, %0;" : "+r"(pB3));
            {
                __half2 tA0 = __hadd2(*(__half2*)&pA0, *(__half2*)&pA2);
                __half2 tA1 = __hadd2(*(__half2*)&pA1, *(__half2*)&pA3);
                __half2 tB0 = __hadd2(*(__half2*)&pB0, *(__half2*)&pB2);
                __half2 tB1 = __hadd2(*(__half2*)&pB1, *(__half2*)&pB3);
                float2 fA0 = __half22float2(tA0);
                float2 fA1 = __half22float2(tA1);
                float2 fB0 = __half22float2(tB0);
                float2 fB1 = __half22float2(tB1);
                l0 += fA0.x + fA0.y;
                l1 += fA1.x + fA1.y;
                l2 += fB0.x + fB0.y;
                l3 += fB1.x + fB1.y;
            }
            u32 v0, v1, v2, v3;
            asm volatile("ldmatrix.sync.aligned.m8n8.x4.trans.shared.b16 {%0,%1,%2,%3}, [%4];"
                : "=r"(v0), "=r"(v1), "=r"(v2), "=r"(v3) : "r"(vB + kc * 768));
            asm volatile("mma.sync.aligned.m16n8k16.row.col.f32.f16.f16.f32 "
                "{%0,%1,%2,%3}, {%4,%5,%6,%7}, {%8,%9}, {%0,%1,%2,%3};"
                : "+f"(oA[0]), "+f"(oA[1]), "+f"(oA[2]), "+f"(oA[3])
                : "r"(pA0), "r"(pA1), "r"(pA2), "r"(pA3), "r"(v0), "r"(v1));
            asm volatile("mma.sync.aligned.m16n8k16.row.col.f32.f16.f16.f32 "
                "{%0,%1,%2,%3}, {%4,%5,%6,%7}, {%8,%9}, {%0,%1,%2,%3};"
                : "+f"(oA[4]), "+f"(oA[5]), "+f"(oA[6]), "+f"(oA[7])
                : "r"(pA0), "r"(pA1), "r"(pA2), "r"(pA3), "r"(v2), "r"(v3));
            asm volatile("mma.sync.aligned.m16n8k16.row.col.f32.f16.f16.f32 "
                "{%0,%1,%2,%3}, {%4,%5,%6,%7}, {%8,%9}, {%0,%1,%2,%3};"
                : "+f"(oB[0]), "+f"(oB[1]), "+f"(oB[2]), "+f"(oB[3])
                : "r"(pB0), "r"(pB1), "r"(pB2), "r"(pB3), "r"(v0), "r"(v1));
            asm volatile("mma.sync.aligned.m16n8k16.row.col.f32.f16.f16.f32 "
                "{%0,%1,%2,%3}, {%4,%5,%6,%7}, {%8,%9}, {%0,%1,%2,%3};"
                : "+f"(oB[4]), "+f"(oB[5]), "+f"(oB[6]), "+f"(oB[7])
                : "r"(pB0), "r"(pB1), "r"(pB2), "r"(pB3), "r"(v2), "r"(v3));
        }
        bufc = (bufc + 1 == 3) ? 0 : bufc + 1;
    }
    #undef ISSUE

    // reduce l across the quad (keys partitioned over w=0..3)
    l0 += __shfl_xor_sync(0xffffffffu, l0, 1);
    l0 += __shfl_xor_sync(0xffffffffu, l0, 2);
    l1 += __shfl_xor_sync(0xffffffffu, l1, 1);
    l1 += __shfl_xor_sync(0xffffffffu, l1, 2);
    l2 += __shfl_xor_sync(0xffffffffu, l2, 1);
    l2 += __shfl_xor_sync(0xffffffffu, l2, 2);
    l3 += __shfl_xor_sync(0xffffffffu, l3, 1);
    l3 += __shfl_xor_sync(0xffffffffu, l3, 2);

    int row0 = qt * TJ + wid * 32 + g;
    size_t pb = ((size_t)(bh * NSPLIT + sp) * N_ + row0) * DH;
    float* o0 = g_accP + pb;                        // row0
    float* o1 = g_accP + pb + (size_t)8 * DH;       // row0+8
    float* o2 = g_accP + pb + (size_t)16 * DH;      // row0+16
    float* o3 = g_accP + pb + (size_t)24 * DH;      // row0+24
    o0[2 * w]     = oA[0]; o0[2 * w + 1]     = oA[1];
    o0[8 + 2 * w] = oA[4]; o0[8 + 2 * w + 1] = oA[5];
    o1[2 * w]     = oA[2]; o1[2 * w + 1]     = oA[3];
    o1[8 + 2 * w] = oA[6]; o1[8 + 2 * w + 1] = oA[7];
    o2[2 * w]     = oB[0]; o2[2 * w + 1]     = oB[1];
    o2[8 + 2 * w] = oB[4]; o2[8 + 2 * w + 1] = oB[5];
    o3[2 * w]     = oB[2]; o3[2 * w + 1]     = oB[3];
    o3[8 + 2 * w] = oB[6]; o3[8 + 2 * w + 1] = oB[7];
    if (w == 0) {
        size_t lb = (size_t)(bh * NSPLIT + sp) * N_ + row0;
        g_lP[lb]      = l0;
        g_lP[lb + 8]  = l1;
        g_lP[lb + 16] = l2;
        g_lP[lb + 24] = l3;
    }
}

// ---- K4: combine splits + residual + LN2 + out proj + residual ----
__global__ void k_epi(const float* __restrict__ x, const float* __restrict__ wout,
                      const float* __restrict__ bout, const float* __restrict__ g2,
                      const float* __restrict__ b2, float* __restrict__ out) {
    __shared__ float shv[8 * DIM];
    __shared__ float sy[8 * DIM];
    int tok0 = blockIdx.x * 8;
    int tid = threadIdx.x;
    for (int i = tid; i < 8 * DIM; i += 256) {
        int gt = tok0 + (i >> 7);
        int d = i & 127;
        int b = gt >> 9, t = gt & 511;
        int bh = b * H_ + (d >> 4);
        int dd = d & 15;
        float num = 0.f, l = 0.f;
        #pragma unroll
        for (int s = 0; s < NSPLIT; s++) {
            num += g_accP[((size_t)(bh * NSPLIT + s) * N_ + t) * DH + dd];
            l   += g_lP[(size_t)(bh * NSPLIT + s) * N_ + t];
        }
        shv[i] = __fdividef(num, l) + x[(size_t)gt * DIM + d];
    }
    __syncthreads();
    int w = tid >> 5, lane = tid & 31;
    float v0 = shv[w * DIM + lane], v1 = shv[w * DIM + lane + 32];
    float v2 = shv[w * DIM + lane + 64], v3 = shv[w * DIM + lane + 96];
    float sum = v0 + v1 + v2 + v3;
    float sq = v0 * v0 + v1 * v1 + v2 * v2 + v3 * v3;
    #pragma unroll
    for (int o = 16; o; o >>= 1) {
        sum += __shfl_xor_sync(~0u, sum, o);
        sq  += __shfl_xor_sync(~0u, sq, o);
    }
    float mu = sum * (1.0f / 128.0f);
    float var = sq * (1.0f / 128.0f) - mu * mu;
    float r = rsqrtf(var + 1e-5f);
    sy[w * DIM + lane]      = (v0 - mu) * r * g2[lane]      + b2[lane];
    sy[w * DIM + lane + 32] = (v1 - mu) * r * g2[lane + 32] + b2[lane + 32];
    sy[w * DIM + lane + 64] = (v2 - mu) * r * g2[lane + 64] + b2[lane + 64];
    sy[w * DIM + lane + 96] = (v3 - mu) * r * g2[lane + 96] + b2[lane + 96];
    __syncthreads();
    int o = tid & 127, grp = tid >> 7;
    const float* wrow = wout + (size_t)o * DIM;
    int t0 = grp * 4;
    float a0 = 0.f, a1 = 0.f, a2 = 0.f, a3 = 0.f;
    for (int d = 0; d < DIM; d++) {
        float wv = wrow[d];
        a0 = fmaf(wv, sy[(t0 + 0) * DIM + d], a0);
        a1 = fmaf(wv, sy[(t0 + 1) * DIM + d], a1);
        a2 = fmaf(wv, sy[(t0 + 2) * DIM + d], a2);
        a3 = fmaf(wv, sy[(t0 + 3) * DIM + d], a3);
    }
    float bo = bout[o];
    out[(size_t)(tok0 + t0 + 0) * DIM + o] = a0 + bo + shv[(t0 + 0) * DIM + o];
    out[(size_t)(tok0 + t0 + 1) * DIM + o] = a1 + bo + shv[(t0 + 1) * DIM + o];
    out[(size_t)(tok0 + t0 + 2) * DIM + o] = a2 + bo + shv[(t0 + 2) * DIM + o];
    out[(size_t)(tok0 + t0 + 3) * DIM + o] = a3 + bo + shv[(t0 + 3) * DIM + o];
}

extern "C" void kernel_launch(void* const* d_in, const int* in_sizes, int n_in,
                              void* d_out, int out_size) {
    const float* x      = (const float*)d_in[0];
    const float* mem_kv = (const float*)d_in[1];
    const float* w_q    = (const float*)d_in[2];
    const float* w_kv   = (const float*)d_in[3];
    const float* w_out  = (const float*)d_in[4];
    const float* b_out  = (const float*)d_in[5];
    const float* g1     = (const float*)d_in[6];
    const float* b1     = (const float*)d_in[7];
    const float* g2     = (const float*)d_in[8];
    const float* b2     = (const float*)d_in[9];

    float* out = (float*)d_out;                  // [4,512,128]
    float* memkv_out = out + (size_t)NTOK * DIM; // [4,8,8704,32]

    k_head<<<464, 256>>>(x, g1, b1, w_q, w_kv, memkv_out);
    k_mid<<<9728, 256>>>((const float4*)mem_kv, (float4*)memkv_out);
    k_attn<<<dim3(BH, 4, NSPLIT), 128>>>();
    k_epi<<<NTOK / 8, 256>>>(x, w_out, b_out, g2, b2, out);
}

// round 16
// speedup vs baseline: 1.3695x; 1.2909x over previous
#include <cuda_runtime.h>
#include <cuda_fp16.h>

typedef unsigned int u32;

#define B_ 4
#define N_ 512
#define H_ 8
#define DH 16
#define DIM 128
#define M_ 8192
#define J_ 8704
#define BH 32
#define NTOK 2048
#define TJ 128
#define NSPLIT 4
#define NT4 17           // (J_/TJ)/NSPLIT
#define LOG2E 1.44269504f
#define NSHIFT (-8.65617025f)   /* = -6 * log2(e), fixed softmax shift */
#define BUFB 6144               /* bytes per K (or V) smem buffer: TJ*24*2 */

// ---- scratch (static device arrays: no allocation) ----
__device__ __align__(16) float  g_qraw[NTOK * DIM];
__device__ __align__(16) __half g_qh[BH * N_ * DH];
__device__ __align__(16) float  g_cost[J_ * 8];
__device__ __align__(16) float  g_sint[J_ * 8];
__device__ __align__(16) __half g_kh[(size_t)BH * J_ * DH];  // rotated K, f16
__device__ __align__(16) __half g_vh[(size_t)BH * J_ * DH];  // V, f16
__device__ __align__(16) float  g_accP[(size_t)BH * NSPLIT * N_ * DH]; // partial numerators
__device__ __align__(16) float  g_lP[BH * NSPLIT * N_];               // partial denominators

__device__ __forceinline__ u32 smem_u32(const void* p) {
    u32 a;
    asm("{ .reg .u64 t; cvta.to.shared.u64 t, %1; cvt.u32.u64 %0, t; }"
        : "=r"(a) : "l"(p));
    return a;
}

// ---- K1 (fused head): rotary tables (blocks 192..463) +
//      LN1-inline Q/KV projection GEMM (blocks 0..191) ----
__global__ void __launch_bounds__(256) k_head(const float* __restrict__ x,
                                              const float* __restrict__ g1,
                                              const float* __restrict__ b1,
                                              const float* __restrict__ wq,
                                              const float* __restrict__ wkv,
                                              float* __restrict__ memkv_out) {
    __shared__ float sw[128 * 68];   // weight tile [128 out][64 k], stride 68
    __shared__ float sx[32 * 68];    // normalized x tile [32 tok][64 k]
    __shared__ float smu[32], srv[32];
    const int tid = threadIdx.x;

    if (blockIdx.x >= 192) {
        // rotary tables: 272 blocks * 256 = J_*8 exactly
        int i = (blockIdx.x - 192) * 256 + tid;
        int j = i >> 3, f = i & 7;
        float invf = exp2f((float)f * -1.66096404744f);  // 10000^(-f/8)
        float s, c;
        sincosf((float)j * invf, &s, &c);
        g_cost[i] = c;
        g_sint[i] = s;
        return;
    }

    const int pb = blockIdx.x;
    const int t0 = (pb & 63) * 32;
    const int ch = pb >> 6;
    const float* wsrc = (ch == 0) ? wq : (wkv + (size_t)(ch - 1) * 128 * DIM);
    const int og = tid & 31, tg = tid >> 5;

    // LN stats: 8 lanes per token
    {
        int tok = tid >> 3, sub = tid & 7;
        const float* xr = x + (size_t)(t0 + tok) * DIM + sub * 16;
        float sum = 0.f, sq = 0.f;
        #pragma unroll
        for (int i = 0; i < 4; i++) {
            float4 v = *(const float4*)(xr + i * 4);
            sum += v.x + v.y + v.z + v.w;
            sq  += v.x * v.x + v.y * v.y + v.z * v.z + v.w * v.w;
        }
        #pragma unroll
        for (int o = 4; o; o >>= 1) {
            sum += __shfl_xor_sync(~0u, sum, o);
            sq  += __shfl_xor_sync(~0u, sq, o);
        }
        float mu = sum * (1.0f / 128.0f);
        float var = sq * (1.0f / 128.0f) - mu * mu;
        if (sub == 0) { smu[tok] = mu; srv[tok] = rsqrtf(var + 1e-5f); }
    }
    __syncthreads();

    float acc[4][4];
    #pragma unroll
    for (int t = 0; t < 4; t++)
        #pragma unroll
        for (int o = 0; o < 4; o++) acc[t][o] = 0.f;

    for (int kc = 0; kc < 2; kc++) {
        #pragma unroll
        for (int i = 0; i < 8; i++) {
            int idx = tid + i * 256;
            int o = idx >> 4, k4 = (idx & 15) * 4;
            *(float4*)&sw[o * 68 + k4] =
                *(const float4*)&wsrc[(size_t)o * DIM + kc * 64 + k4];
        }
        #pragma unroll
        for (int i = 0; i < 2; i++) {
            int idx = tid + i * 256;
            int t = idx >> 4, k4 = (idx & 15) * 4;
            float4 raw = *(const float4*)&x[(size_t)(t0 + t) * DIM + kc * 64 + k4];
            float4 gg = *(const float4*)&g1[kc * 64 + k4];
            float4 bb = *(const float4*)&b1[kc * 64 + k4];
            float mu = smu[t], rv = srv[t];
            float4 nn;
            nn.x = (raw.x - mu) * rv * gg.x + bb.x;
            nn.y = (raw.y - mu) * rv * gg.y + bb.y;
            nn.z = (raw.z - mu) * rv * gg.z + bb.z;
            nn.w = (raw.w - mu) * rv * gg.w + bb.w;
            *(float4*)&sx[t * 68 + k4] = nn;
        }
        __syncthreads();
        const float* swb = sw + og * 68;
        const float* sxb = sx + tg * 4 * 68;
        #pragma unroll
        for (int ks = 0; ks < 16; ks++) {
            float4 w0 = *(const float4*)&swb[0 * 2176 + ks * 4];
            float4 w1 = *(const float4*)&swb[1 * 2176 + ks * 4];
            float4 w2 = *(const float4*)&swb[2 * 2176 + ks * 4];
            float4 w3 = *(const float4*)&swb[3 * 2176 + ks * 4];
            #pragma unroll
            for (int t = 0; t < 4; t++) {
                float4 xv = *(const float4*)&sxb[t * 68 + ks * 4];
                acc[t][0] += xv.x * w0.x + xv.y * w0.y + xv.z * w0.z + xv.w * w0.w;
                acc[t][1] += xv.x * w1.x + xv.y * w1.y + xv.z * w1.z + xv.w * w1.w;
                acc[t][2] += xv.x * w2.x + xv.y * w2.y + xv.z * w2.z + xv.w * w2.w;
                acc[t][3] += xv.x * w3.x + xv.y * w3.y + xv.z * w3.z + xv.w * w3.w;
            }
        }
        __syncthreads();
    }

    #pragma unroll
    for (int t = 0; t < 4; t++) {
        int gt = t0 + tg * 4 + t;
        if (ch == 0) {
            #pragma unroll
            for (int o = 0; o < 4; o++)
                g_qraw[(size_t)gt * DIM + og + 32 * o] = acc[t][o];
        } else {
            int b = gt >> 9, tt = gt & 511;
            #pragma unroll
            for (int o = 0; o < 4; o++) {
                int h = (ch - 1) * 4 + o;
                memkv_out[((size_t)(b * H_ + h) * J_ + (M_ + tt)) * 32 + og] = acc[t][o];
            }
        }
    }
}

// ---- helper: rotate+convert 32 staged KV rows from smem into g_kh/g_vh ----
__device__ __forceinline__ void rotconv_rows(const float* s, int r, int q, int j,
                                             size_t drow) {
    if (q < 4) {
        u32 out0, out1;
        #pragma unroll
        for (int i = 0; i < 2; i++) {
            int d0 = 4 * q + 2 * i, d1 = d0 + 1;
            float v0 = s[r * 36 + d0], p0 = s[r * 36 + (d0 ^ 8)];
            float v1 = s[r * 36 + d1], p1 = s[r * 36 + (d1 ^ 8)];
            float r0 = v0 * g_cost[j * 8 + (d0 & 7)] + ((d0 < 8) ? -p0 : p0) * g_sint[j * 8 + (d0 & 7)];
            float r1 = v1 * g_cost[j * 8 + (d1 & 7)] + ((d1 < 8) ? -p1 : p1) * g_sint[j * 8 + (d1 & 7)];
            u32 h2; asm("cvt.rn.f16x2.f32 %0, %1, %2;" : "=r"(h2) : "f"(r1), "f"(r0));
            if (i == 0) out0 = h2; else out1 = h2;
        }
        *(uint2*)((u32*)g_kh + drow * 8 + 2 * q) = make_uint2(out0, out1);
    } else {
        int qq = q - 4;
        u32 out0, out1;
        #pragma unroll
        for (int i = 0; i < 2; i++) {
            int d0 = 16 + 4 * qq + 2 * i;
            u32 h2; asm("cvt.rn.f16x2.f32 %0, %1, %2;"
                        : "=r"(h2) : "f"(s[r * 36 + d0 + 1]), "f"(s[r * 36 + d0]));
            if (i == 0) out0 = h2; else out1 = h2;
        }
        *(uint2*)((u32*)g_vh + drow * 8 + 2 * qq) = make_uint2(out0, out1);
    }
}

// ---- K2 (fused): prep (old cache) + newkv + qrot ----
__global__ void __launch_bounds__(256) k_mid(const float4* __restrict__ src,
                                             float4* __restrict__ dst) {
    int blk = blockIdx.x;
    int tid = threadIdx.x;
    if (blk < 8192) {
        __shared__ float s[32 * 36];
        int bh = blk >> 8;
        int j0 = (blk & 255) << 5;
        int r = tid >> 3, c = tid & 7;
        size_t srow = (size_t)bh * M_ + j0 + r;
        size_t drow = (size_t)bh * J_ + j0 + r;
        float4 v = src[srow * 8 + c];
        dst[drow * 8 + c] = v;
        *(float4*)(s + r * 36 + c * 4) = v;
        __syncthreads();
        rotconv_rows(s, r, tid & 7, j0 + r, drow);
        return;
    }
    if (blk < 8704) {
        __shared__ float s2[32 * 36];
        int b2 = blk - 8192;
        int bh = b2 >> 4;
        int j0 = M_ + ((b2 & 15) << 5);
        int r = tid >> 3, c = tid & 7;
        size_t drow = (size_t)bh * J_ + j0 + r;
        float4 v = dst[drow * 8 + c];
        *(float4*)(s2 + r * 36 + c * 4) = v;
        __syncthreads();
        rotconv_rows(s2, r, tid & 7, j0 + r, drow);
        return;
    }
    int i = (blk - 8704) * 256 + tid;      // < NTOK*DIM
    int d = i & 127, gt = i >> 7;
    int dd = d & 15, hh = d >> 4;
    int b = gt >> 9, tt = gt & 511;
    int f = dd & 7;
    int pos = M_ + tt;
    float c = g_cost[pos * 8 + f];
    float s = g_sint[pos * 8 + f];
    float v = g_qraw[i];
    float vp = g_qraw[((size_t)gt << 7) + (hh << 4) + (dd ^ 8)];
    float rh = (dd < 8) ? -vp : vp;
    float q = (v * c + rh * s) * (0.25f * LOG2E);
    g_qh[((size_t)(b * H_ + hh) * N_ + tt) * DH + dd] = __float2half(q);
}

// ---- K3: attention, m32 Q-tile per warp (R13 config: best known),
//      4 warps/CTA, NSPLIT=4 -> 512 CTAs; triple-buffered cp.async ----
__global__ void __launch_bounds__(128, 4) k_attn() {
    __shared__ __half sK[3][TJ * 24];   // K tiles, 48B row stride
    __shared__ __half sV[3][TJ * 24];   // V tiles, 48B row stride
    const int bh = blockIdx.x, qt = blockIdx.y, sp = blockIdx.z;
    const int tid = threadIdx.x, wid = tid >> 5, lane = tid & 31;
    const int g = lane >> 2, w = lane & 3;

    // two resident Q A-fragments: rows qt*128 + wid*32 + {g,g+8} and +16
    const __half* qp = g_qh + ((size_t)(bh * N_ + qt * TJ + wid * 32)) * DH;
    u32 qa0 = *(const u32*)(qp + (size_t)g * DH + 2 * w);
    u32 qa1 = *(const u32*)(qp + (size_t)(g + 8) * DH + 2 * w);
    u32 qa2 = *(const u32*)(qp + (size_t)g * DH + 2 * w + 8);
    u32 qa3 = *(const u32*)(qp + (size_t)(g + 8) * DH + 2 * w + 8);
    const __half* qp2 = qp + (size_t)16 * DH;
    u32 qb0 = *(const u32*)(qp2 + (size_t)g * DH + 2 * w);
    u32 qb1 = *(const u32*)(qp2 + (size_t)(g + 8) * DH + 2 * w);
    u32 qb2 = *(const u32*)(qp2 + (size_t)g * DH + 2 * w + 8);
    u32 qb3 = *(const u32*)(qp2 + (size_t)(g + 8) * DH + 2 * w + 8);

    float oA[8], oB[8];
    #pragma unroll
    for (int i = 0; i < 8; i++) { oA[i] = 0.f; oB[i] = 0.f; }
    float l0 = 0.f, l1 = 0.f, l2 = 0.f, l3 = 0.f;

    const __half hns = __float2half(NSHIFT);
    const u32 ns2 = ((u32)__half_as_ushort(hns) << 16) | __half_as_ushort(hns);

    // staging: thread -> key row tid (32B K row + 32B V row via 2+2 cp.async)
    const int ki = tid;
    const int jbase = sp * NT4 * TJ;
    const u32* kg = (const u32*)g_kh + (size_t)bh * J_ * 8;
    const u32* vg = (const u32*)g_vh + (size_t)bh * J_ * 8;

    const u32 sKa = smem_u32(sK), sVa = smem_u32(sV);
    const u32 kdst = sKa + (u32)(ki * 48);
    const u32 vdst = sVa + (u32)(ki * 48);

    // ldmatrix lane addresses (buffer 0 base)
    const int r8 = lane & 7, m4 = lane >> 3;
    const u32 kaddr0 = sKa + (u32)((((m4 >> 1) * 8 + r8) * 48) + (m4 & 1) * 16);
    const u32 vaddr0 = sVa + (u32)((((m4 & 1) * 8 + r8) * 48) + (m4 >> 1) * 16);

    #define ISSUE(buf, tile) do {                                                   \
        size_t jrow = (size_t)(jbase + (tile) * TJ + ki) * 8;                        \
        asm volatile("cp.async.ca.shared.global [%0], [%1], 16;"                    \
                     :: "r"(kdst + (buf) * BUFB), "l"(kg + jrow));                   \
        asm volatile("cp.async.ca.shared.global [%0], [%1], 16;"                    \
                     :: "r"(kdst + (buf) * BUFB + 16), "l"(kg + jrow + 4));          \
        asm volatile("cp.async.ca.shared.global [%0], [%1], 16;"                    \
                     :: "r"(vdst + (buf) * BUFB), "l"(vg + jrow));                   \
        asm volatile("cp.async.ca.shared.global [%0], [%1], 16;"                    \
                     :: "r"(vdst + (buf) * BUFB + 16), "l"(vg + jrow + 4));          \
        asm volatile("cp.async.commit_group;");                                     \
    } while (0)

    ISSUE(0, 0);
    ISSUE(1, 1);

    int bufc = 0;
    for (int t = 0; t < NT4; t++) {
        if (t + 1 < NT4) {
            asm volatile("cp.async.wait_group 1;");
        } else {
            asm volatile("cp.async.wait_group 0;");
        }
        __syncthreads();   // tile t visible; all warps done with tile t-1
        if (t + 2 < NT4) {
            int bslot = bufc + 2; if (bslot >= 3) bslot -= 3;
            ISSUE(bslot, t + 2);
        }

        const u32 kB = kaddr0 + bufc * BUFB;
        const u32 vB = vaddr0 + bufc * BUFB;
        #pragma unroll
        for (int kc = 0; kc < 8; kc++) {
            u32 kb0, kb1, kb2, kb3;
            asm volatile("ldmatrix.sync.aligned.m8n8.x4.shared.b16 {%0,%1,%2,%3}, [%4];"
                : "=r"(kb0), "=r"(kb1), "=r"(kb2), "=r"(kb3) : "r"(kB + kc * 768));
            u32 pA0, pA1, pA2, pA3, pB0, pB1, pB2, pB3;
            asm volatile("mma.sync.aligned.m16n8k16.row.col.f16.f16.f16.f16 "
                "{%0,%1}, {%2,%3,%4,%5}, {%6,%7}, {%8,%9};"
                : "=r"(pA0), "=r"(pA1)
                : "r"(qa0), "r"(qa1), "r"(qa2), "r"(qa3), "r"(kb0), "r"(kb1),
                  "r"(ns2), "r"(ns2));
            asm volatile("mma.sync.aligned.m16n8k16.row.col.f16.f16.f16.f16 "
                "{%0,%1}, {%2,%3,%4,%5}, {%6,%7}, {%8,%9};"
                : "=r"(pA2), "=r"(pA3)
                : "r"(qa0), "r"(qa1), "r"(qa2), "r"(qa3), "r"(kb2), "r"(kb3),
                  "r"(ns2), "r"(ns2));
            asm volatile("mma.sync.aligned.m16n8k16.row.col.f16.f16.f16.f16 "
                "{%0,%1}, {%2,%3,%4,%5}, {%6,%7}, {%8,%9};"
                : "=r"(pB0), "=r"(pB1)
                : "r"(qb0), "r"(qb1), "r"(qb2), "r"(qb3), "r"(kb0), "r"(kb1),
                  "r"(ns2), "r"(ns2));
            asm volatile("mma.sync.aligned.m16n8k16.row.col.f16.f16.f16.f16 "
                "{%0,%1}, {%2,%3,%4,%5}, {%6,%7}, {%8,%9};"
                : "=r"(pB2), "=r"(pB3)
                : "r"(qb0), "r"(qb1), "r"(qb2), "r"(qb3), "r"(kb2), "r"(kb3),
                  "r"(ns2), "r"(ns2));
            asm("ex2.approx.f16x2 %0, %0;" : "+r"(pA0));
            asm("ex2.approx.f16x2 %0, %0;" : "+r"(pA1));
            asm("ex2.approx.f16x2 %0, %0;" : "+r"(pA2));
            asm("ex2.approx.f16x2 %0, %0;" : "+r"(pA3));
            asm("ex2.approx.f16x2 %0, %0;" : "+r"(pB0));
            asm("ex2.approx.f16x2 %0, %0;" : "+r"(pB1));
            asm("ex2.approx.f16x2 %0, %0;" : "+r"(pB2));
            asm("ex2.approx.f16x2 %0, %0;" : "+r"(pB3));
            {
                __half2 tA0 = __hadd2(*(__half2*)&pA0, *(__half2*)&pA2);
                __half2 tA1 = __hadd2(*(__half2*)&pA1, *(__half2*)&pA3);
                __half2 tB0 = __hadd2(*(__half2*)&pB0, *(__half2*)&pB2);
                __half2 tB1 = __hadd2(*(__half2*)&pB1, *(__half2*)&pB3);
                float2 fA0 = __half22float2(tA0);
                float2 fA1 = __half22float2(tA1);
                float2 fB0 = __half22float2(tB0);
                float2 fB1 = __half22float2(tB1);
                l0 += fA0.x + fA0.y;
                l1 += fA1.x + fA1.y;
                l2 += fB0.x + fB0.y;
                l3 += fB1.x + fB1.y;
            }
            u32 v0, v1, v2, v3;
            asm volatile("ldmatrix.sync.aligned.m8n8.x4.trans.shared.b16 {%0,%1,%2,%3}, [%4];"
                : "=r"(v0), "=r"(v1), "=r"(v2), "=r"(v3) : "r"(vB + kc * 768));
            asm volatile("mma.sync.aligned.m16n8k16.row.col.f32.f16.f16.f32 "
                "{%0,%1,%2,%3}, {%4,%5,%6,%7}, {%8,%9}, {%0,%1,%2,%3};"
                : "+f"(oA[0]), "+f"(oA[1]), "+f"(oA[2]), "+f"(oA[3])
                : "r"(pA0), "r"(pA1), "r"(pA2), "r"(pA3), "r"(v0), "r"(v1));
            asm volatile("mma.sync.aligned.m16n8k16.row.col.f32.f16.f16.f32 "
                "{%0,%1,%2,%3}, {%4,%5,%6,%7}, {%8,%9}, {%0,%1,%2,%3};"
                : "+f"(oA[4]), "+f"(oA[5]), "+f"(oA[6]), "+f"(oA[7])
                : "r"(pA0), "r"(pA1), "r"(pA2), "r"(pA3), "r"(v2), "r"(v3));
            asm volatile("mma.sync.aligned.m16n8k16.row.col.f32.f16.f16.f32 "
                "{%0,%1,%2,%3}, {%4,%5,%6,%7}, {%8,%9}, {%0,%1,%2,%3};"
                : "+f"(oB[0]), "+f"(oB[1]), "+f"(oB[2]), "+f"(oB[3])
                : "r"(pB0), "r"(pB1), "r"(pB2), "r"(pB3), "r"(v0), "r"(v1));
            asm volatile("mma.sync.aligned.m16n8k16.row.col.f32.f16.f16.f32 "
                "{%0,%1,%2,%3}, {%4,%5,%6,%7}, {%8,%9}, {%0,%1,%2,%3};"
                : "+f"(oB[4]), "+f"(oB[5]), "+f"(oB[6]), "+f"(oB[7])
                : "r"(pB0), "r"(pB1), "r"(pB2), "r"(pB3), "r"(v2), "r"(v3));
        }
        bufc = (bufc + 1 == 3) ? 0 : bufc + 1;
    }
    #undef ISSUE

    // reduce l across the quad (keys partitioned over w=0..3)
    l0 += __shfl_xor_sync(0xffffffffu, l0, 1);
    l0 += __shfl_xor_sync(0xffffffffu, l0, 2);
    l1 += __shfl_xor_sync(0xffffffffu, l1, 1);
    l1 += __shfl_xor_sync(0xffffffffu, l1, 2);
    l2 += __shfl_xor_sync(0xffffffffu, l2, 1);
    l2 += __shfl_xor_sync(0xffffffffu, l2, 2);
    l3 += __shfl_xor_sync(0xffffffffu, l3, 1);
    l3 += __shfl_xor_sync(0xffffffffu, l3, 2);

    int row0 = qt * TJ + wid * 32 + g;
    size_t pb = ((size_t)(bh * NSPLIT + sp) * N_ + row0) * DH;
    float* o0 = g_accP + pb;                        // row0
    float* o1 = g_accP + pb + (size_t)8 * DH;       // row0+8
    float* o2 = g_accP + pb + (size_t)16 * DH;      // row0+16
    float* o3 = g_accP + pb + (size_t)24 * DH;      // row0+24
    o0[2 * w]     = oA[0]; o0[2 * w + 1]     = oA[1];
    o0[8 + 2 * w] = oA[4]; o0[8 + 2 * w + 1] = oA[5];
    o1[2 * w]     = oA[2]; o1[2 * w + 1]     = oA[3];
    o1[8 + 2 * w] = oA[6]; o1[8 + 2 * w + 1] = oA[7];
    o2[2 * w]     = oB[0]; o2[2 * w + 1]     = oB[1];
    o2[8 + 2 * w] = oB[4]; o2[8 + 2 * w + 1] = oB[5];
    o3[2 * w]     = oB[2]; o3[2 * w + 1]     = oB[3];
    o3[8 + 2 * w] = oB[6]; o3[8 + 2 * w + 1] = oB[7];
    if (w == 0) {
        size_t lb = (size_t)(bh * NSPLIT + sp) * N_ + row0;
        g_lP[lb]      = l0;
        g_lP[lb + 8]  = l1;
        g_lP[lb + 16] = l2;
        g_lP[lb + 24] = l3;
    }
}

// ---- K4: epilogue as blocked smem GEMM.
//      grid (64 token-tiles of 32, 2 output halves of 64), 256 threads.
//      combine + residual -> LN2 -> y @ wout^T (coalesced staging) + bias + res ----
__global__ void __launch_bounds__(256) k_epi(const float* __restrict__ x,
                      const float* __restrict__ wout,
                      const float* __restrict__ bout, const float* __restrict__ g2,
                      const float* __restrict__ b2, float* __restrict__ out) {
    __shared__ float R[32 * 132];    // shv, then sy (in-place normalize)
    __shared__ float sw[64 * 36];    // wout tile [64 out][32 k], stride 36
    __shared__ float smu[32], srv[32];
    const int tok0 = blockIdx.x * 32;
    const int oc = blockIdx.y;       // output half: cols oc*64 .. oc*64+63
    const int tid = threadIdx.x;
    const int og = tid & 31, tg = tid >> 5;

    // 1. combine splits + residual -> R (stride 132)
    for (int i = tid; i < 32 * 128; i += 256) {
        int tt = i >> 7, d = i & 127;
        int gt = tok0 + tt;
        int b = gt >> 9, t = gt & 511;
        int bh = b * H_ + (d >> 4);
        int dd = d & 15;
        float num = 0.f, l = 0.f;
        #pragma unroll
        for (int s = 0; s < NSPLIT; s++) {
            num += g_accP[((size_t)(bh * NSPLIT + s) * N_ + t) * DH + dd];
            l   += g_lP[(size_t)(bh * NSPLIT + s) * N_ + t];
        }
        R[tt * 132 + d] = __fdividef(num, l) + x[(size_t)gt * DIM + d];
    }
    __syncthreads();

    // 2. LN2 stats: 8 lanes per token
    {
        int tok = tid >> 3, sub = tid & 7;
        const float* rr = R + tok * 132 + sub * 16;
        float sum = 0.f, sq = 0.f;
        #pragma unroll
        for (int i = 0; i < 4; i++) {
            float4 v = *(const float4*)(rr + i * 4);
            sum += v.x + v.y + v.z + v.w;
            sq  += v.x * v.x + v.y * v.y + v.z * v.z + v.w * v.w;
        }
        #pragma unroll
        for (int o = 4; o; o >>= 1) {
            sum += __shfl_xor_sync(~0u, sum, o);
            sq  += __shfl_xor_sync(~0u, sq, o);
        }
        float mu = sum * (1.0f / 128.0f);
        float var = sq * (1.0f / 128.0f) - mu * mu;
        if (sub == 0) { smu[tok] = mu; srv[tok] = rsqrtf(var + 1e-5f); }
    }
    __syncthreads();

    // 3. park residuals in registers, then normalize R in place
    float res[4][2];
    #pragma unroll
    for (int t = 0; t < 4; t++)
        #pragma unroll
        for (int o = 0; o < 2; o++)
            res[t][o] = R[(tg * 4 + t) * 132 + oc * 64 + og + 32 * o];
    __syncthreads();   // all residual reads complete before overwrite
    for (int i = tid; i < 32 * 128; i += 256) {
        int tt = i >> 7, d = i & 127;
        float v = R[tt * 132 + d];
        R[tt * 132 + d] = (v - smu[tt]) * srv[tt] * g2[d] + b2[d];
    }
    __syncthreads();

    // 4. GEMM: 4 k-chunks of 32
    float acc[4][2];
    #pragma unroll
    for (int t = 0; t < 4; t++) { acc[t][0] = 0.f; acc[t][1] = 0.f; }
    const float* wbase = wout + (size_t)(oc * 64) * DIM;
    for (int kc = 0; kc < 4; kc++) {
        #pragma unroll
        for (int i = 0; i < 2; i++) {
            int idx = tid + i * 256;
            int o = idx >> 3, k4 = (idx & 7) * 4;
            *(float4*)&sw[o * 36 + k4] =
                *(const float4*)&wbase[(size_t)o * DIM + kc * 32 + k4];
        }
        __syncthreads();
        const float* swb = sw + og * 36;
        const float* sxb = R + tg * 4 * 132 + kc * 32;
        #pragma unroll
        for (int ks = 0; ks < 8; ks++) {
            float4 w0 = *(const float4*)&swb[0 * 1152 + ks * 4];   // out og
            float4 w1 = *(const float4*)&swb[1 * 1152 + ks * 4];   // out og+32
            #pragma unroll
            for (int t = 0; t < 4; t++) {
                float4 xv = *(const float4*)&sxb[t * 132 + ks * 4];
                acc[t][0] += xv.x * w0.x + xv.y * w0.y + xv.z * w0.z + xv.w * w0.w;
                acc[t][1] += xv.x * w1.x + xv.y * w1.y + xv.z * w1.z + xv.w * w1.w;
            }
        }
        __syncthreads();
    }

    // 5. write out = gemm + bias + residual
    #pragma unroll
    for (int t = 0; t < 4; t++) {
        int gt = tok0 + tg * 4 + t;
        #pragma unroll
        for (int o = 0; o < 2; o++) {
            int oo = oc * 64 + og + 32 * o;
            out[(size_t)gt * DIM + oo] = acc[t][o] + bout[oo] + res[t][o];
        }
    }
}

extern "C" void kernel_launch(void* const* d_in, const int* in_sizes, int n_in,
                              void* d_out, int out_size) {
    const float* x      = (const float*)d_in[0];
    const float* mem_kv = (const float*)d_in[1];
    const float* w_q    = (const float*)d_in[2];
    const float* w_kv   = (const float*)d_in[3];
    const float* w_out  = (const float*)d_in[4];
    const float* b_out  = (const float*)d_in[5];
    const float* g1     = (const float*)d_in[6];
    const float* b1     = (const float*)d_in[7];
    const float* g2     = (const float*)d_in[8];
    const float* b2     = (const float*)d_in[9];

    float* out = (float*)d_out;                  // [4,512,128]
    float* memkv_out = out + (size_t)NTOK * DIM; // [4,8,8704,32]

    k_head<<<464, 256>>>(x, g1, b1, w_q, w_kv, memkv_out);
    k_mid<<<9728, 256>>>((const float4*)mem_kv, (float4*)memkv_out);
    k_attn<<<dim3(BH, 4, NSPLIT), 128>>>();
    k_epi<<<dim3(64, 2), 256>>>(x, w_out, b_out, g2, b2, out);
}

// round 17
// speedup vs baseline: 1.4416x; 1.0526x over previous
#include <cuda_runtime.h>
#include <cuda_fp16.h>

typedef unsigned int u32;

#define B_ 4
#define N_ 512
#define H_ 8
#define DH 16
#define DIM 128
#define M_ 8192
#define J_ 8704
#define BH 32
#define NTOK 2048
#define TJ 128
#define NSPLIT 4
#define NT4 17           // (J_/TJ)/NSPLIT
#define LOG2E 1.44269504f
#define NSHIFT (-8.65617025f)   /* = -6 * log2(e), fixed softmax shift */
#define BUFB 6144               /* bytes per K (or V) smem buffer: TJ*24*2 */

// ---- scratch (static device arrays: no allocation) ----
__device__ __align__(16) float  g_qraw[NTOK * DIM];
__device__ __align__(16) __half g_qh[BH * N_ * DH];
__device__ __align__(16) float  g_cost[J_ * 8];
__device__ __align__(16) float  g_sint[J_ * 8];
__device__ __align__(16) __half g_kh[(size_t)BH * J_ * DH];  // rotated K, f16
__device__ __align__(16) __half g_vh[(size_t)BH * J_ * DH];  // V, f16
__device__ __align__(16) float  g_accP[(size_t)BH * NSPLIT * N_ * DH]; // partial numerators
__device__ __align__(16) float  g_lP[BH * NSPLIT * N_];               // partial denominators

__device__ __forceinline__ u32 smem_u32(const void* p) {
    u32 a;
    asm("{ .reg .u64 t; cvta.to.shared.u64 t, %1; cvt.u32.u64 %0, t; }"
        : "=r"(a) : "l"(p));
    return a;
}

// ---- K1 (fused head): rotary tables (blocks 192..463) +
//      LN1-inline Q/KV projection GEMM (blocks 0..191) ----
__global__ void __launch_bounds__(256) k_head(const float* __restrict__ x,
                                              const float* __restrict__ g1,
                                              const float* __restrict__ b1,
                                              const float* __restrict__ wq,
                                              const float* __restrict__ wkv,
                                              float* __restrict__ memkv_out) {
    __shared__ float sw[128 * 68];   // weight tile [128 out][64 k], stride 68
    __shared__ float sx[32 * 68];    // normalized x tile [32 tok][64 k]
    __shared__ float smu[32], srv[32];
    const int tid = threadIdx.x;

    if (blockIdx.x >= 192) {
        // rotary tables: 272 blocks * 256 = J_*8 exactly
        int i = (blockIdx.x - 192) * 256 + tid;
        int j = i >> 3, f = i & 7;
        float invf = exp2f((float)f * -1.66096404744f);  // 10000^(-f/8)
        float s, c;
        sincosf((float)j * invf, &s, &c);
        g_cost[i] = c;
        g_sint[i] = s;
        return;
    }

    const int pb = blockIdx.x;
    const int t0 = (pb & 63) * 32;
    const int ch = pb >> 6;
    const float* wsrc = (ch == 0) ? wq : (wkv + (size_t)(ch - 1) * 128 * DIM);
    const int og = tid & 31, tg = tid >> 5;

    // LN stats: 8 lanes per token
    {
        int tok = tid >> 3, sub = tid & 7;
        const float* xr = x + (size_t)(t0 + tok) * DIM + sub * 16;
        float sum = 0.f, sq = 0.f;
        #pragma unroll
        for (int i = 0; i < 4; i++) {
            float4 v = *(const float4*)(xr + i * 4);
            sum += v.x + v.y + v.z + v.w;
            sq  += v.x * v.x + v.y * v.y + v.z * v.z + v.w * v.w;
        }
        #pragma unroll
        for (int o = 4; o; o >>= 1) {
            sum += __shfl_xor_sync(~0u, sum, o);
            sq  += __shfl_xor_sync(~0u, sq, o);
        }
        float mu = sum * (1.0f / 128.0f);
        float var = sq * (1.0f / 128.0f) - mu * mu;
        if (sub == 0) { smu[tok] = mu; srv[tok] = rsqrtf(var + 1e-5f); }
    }
    __syncthreads();

    float acc[4][4];
    #pragma unroll
    for (int t = 0; t < 4; t++)
        #pragma unroll
        for (int o = 0; o < 4; o++) acc[t][o] = 0.f;

    for (int kc = 0; kc < 2; kc++) {
        #pragma unroll
        for (int i = 0; i < 8; i++) {
            int idx = tid + i * 256;
            int o = idx >> 4, k4 = (idx & 15) * 4;
            *(float4*)&sw[o * 68 + k4] =
                *(const float4*)&wsrc[(size_t)o * DIM + kc * 64 + k4];
        }
        #pragma unroll
        for (int i = 0; i < 2; i++) {
            int idx = tid + i * 256;
            int t = idx >> 4, k4 = (idx & 15) * 4;
            float4 raw = *(const float4*)&x[(size_t)(t0 + t) * DIM + kc * 64 + k4];
            float4 gg = *(const float4*)&g1[kc * 64 + k4];
            float4 bb = *(const float4*)&b1[kc * 64 + k4];
            float mu = smu[t], rv = srv[t];
            float4 nn;
            nn.x = (raw.x - mu) * rv * gg.x + bb.x;
            nn.y = (raw.y - mu) * rv * gg.y + bb.y;
            nn.z = (raw.z - mu) * rv * gg.z + bb.z;
            nn.w = (raw.w - mu) * rv * gg.w + bb.w;
            *(float4*)&sx[t * 68 + k4] = nn;
        }
        __syncthreads();
        const float* swb = sw + og * 68;
        const float* sxb = sx + tg * 4 * 68;
        #pragma unroll
        for (int ks = 0; ks < 16; ks++) {
            float4 w0 = *(const float4*)&swb[0 * 2176 + ks * 4];
            float4 w1 = *(const float4*)&swb[1 * 2176 + ks * 4];
            float4 w2 = *(const float4*)&swb[2 * 2176 + ks * 4];
            float4 w3 = *(const float4*)&swb[3 * 2176 + ks * 4];
            #pragma unroll
            for (int t = 0; t < 4; t++) {
                float4 xv = *(const float4*)&sxb[t * 68 + ks * 4];
                acc[t][0] += xv.x * w0.x + xv.y * w0.y + xv.z * w0.z + xv.w * w0.w;
                acc[t][1] += xv.x * w1.x + xv.y * w1.y + xv.z * w1.z + xv.w * w1.w;
                acc[t][2] += xv.x * w2.x + xv.y * w2.y + xv.z * w2.z + xv.w * w2.w;
                acc[t][3] += xv.x * w3.x + xv.y * w3.y + xv.z * w3.z + xv.w * w3.w;
            }
        }
        __syncthreads();
    }

    #pragma unroll
    for (int t = 0; t < 4; t++) {
        int gt = t0 + tg * 4 + t;
        if (ch == 0) {
            #pragma unroll
            for (int o = 0; o < 4; o++)
                g_qraw[(size_t)gt * DIM + og + 32 * o] = acc[t][o];
        } else {
            int b = gt >> 9, tt = gt & 511;
            #pragma unroll
            for (int o = 0; o < 4; o++) {
                int h = (ch - 1) * 4 + o;
                memkv_out[((size_t)(b * H_ + h) * J_ + (M_ + tt)) * 32 + og] = acc[t][o];
            }
        }
    }
}

// ---- helper: rotate+convert 32 staged KV rows from smem into g_kh/g_vh ----
__device__ __forceinline__ void rotconv_rows(const float* s, int r, int q, int j,
                                             size_t drow) {
    if (q < 4) {
        u32 out0, out1;
        #pragma unroll
        for (int i = 0; i < 2; i++) {
            int d0 = 4 * q + 2 * i, d1 = d0 + 1;
            float v0 = s[r * 36 + d0], p0 = s[r * 36 + (d0 ^ 8)];
            float v1 = s[r * 36 + d1], p1 = s[r * 36 + (d1 ^ 8)];
            float r0 = v0 * g_cost[j * 8 + (d0 & 7)] + ((d0 < 8) ? -p0 : p0) * g_sint[j * 8 + (d0 & 7)];
            float r1 = v1 * g_cost[j * 8 + (d1 & 7)] + ((d1 < 8) ? -p1 : p1) * g_sint[j * 8 + (d1 & 7)];
            u32 h2; asm("cvt.rn.f16x2.f32 %0, %1, %2;" : "=r"(h2) : "f"(r1), "f"(r0));
            if (i == 0) out0 = h2; else out1 = h2;
        }
        *(uint2*)((u32*)g_kh + drow * 8 + 2 * q) = make_uint2(out0, out1);
    } else {
        int qq = q - 4;
        u32 out0, out1;
        #pragma unroll
        for (int i = 0; i < 2; i++) {
            int d0 = 16 + 4 * qq + 2 * i;
            u32 h2; asm("cvt.rn.f16x2.f32 %0, %1, %2;"
                        : "=r"(h2) : "f"(s[r * 36 + d0 + 1]), "f"(s[r * 36 + d0]));
            if (i == 0) out0 = h2; else out1 = h2;
        }
        *(uint2*)((u32*)g_vh + drow * 8 + 2 * qq) = make_uint2(out0, out1);
    }
}

// ---- K2 (fused): prep (old cache) + newkv + qrot ----
__global__ void __launch_bounds__(256) k_mid(const float4* __restrict__ src,
                                             float4* __restrict__ dst) {
    int blk = blockIdx.x;
    int tid = threadIdx.x;
    if (blk < 8192) {
        __shared__ float s[32 * 36];
        int bh = blk >> 8;
        int j0 = (blk & 255) << 5;
        int r = tid >> 3, c = tid & 7;
        size_t srow = (size_t)bh * M_ + j0 + r;
        size_t drow = (size_t)bh * J_ + j0 + r;
        float4 v = src[srow * 8 + c];
        dst[drow * 8 + c] = v;
        *(float4*)(s + r * 36 + c * 4) = v;
        __syncthreads();
        rotconv_rows(s, r, tid & 7, j0 + r, drow);
        return;
    }
    if (blk < 8704) {
        __shared__ float s2[32 * 36];
        int b2 = blk - 8192;
        int bh = b2 >> 4;
        int j0 = M_ + ((b2 & 15) << 5);
        int r = tid >> 3, c = tid & 7;
        size_t drow = (size_t)bh * J_ + j0 + r;
        float4 v = dst[drow * 8 + c];
        *(float4*)(s2 + r * 36 + c * 4) = v;
        __syncthreads();
        rotconv_rows(s2, r, tid & 7, j0 + r, drow);
        return;
    }
    int i = (blk - 8704) * 256 + tid;      // < NTOK*DIM
    int d = i & 127, gt = i >> 7;
    int dd = d & 15, hh = d >> 4;
    int b = gt >> 9, tt = gt & 511;
    int f = dd & 7;
    int pos = M_ + tt;
    float c = g_cost[pos * 8 + f];
    float s = g_sint[pos * 8 + f];
    float v = g_qraw[i];
    float vp = g_qraw[((size_t)gt << 7) + (hh << 4) + (dd ^ 8)];
    float rh = (dd < 8) ? -vp : vp;
    float q = (v * c + rh * s) * (0.25f * LOG2E);
    g_qh[((size_t)(b * H_ + hh) * N_ + tt) * DH + dd] = __float2half(q);
}

// ---- K3: attention, m32 Q-tile per warp (R13 config: best known),
//      4 warps/CTA, NSPLIT=4 -> 512 CTAs; triple-buffered cp.async ----
__global__ void __launch_bounds__(128, 4) k_attn() {
    __shared__ __half sK[3][TJ * 24];   // K tiles, 48B row stride
    __shared__ __half sV[3][TJ * 24];   // V tiles, 48B row stride
    const int bh = blockIdx.x, qt = blockIdx.y, sp = blockIdx.z;
    const int tid = threadIdx.x, wid = tid >> 5, lane = tid & 31;
    const int g = lane >> 2, w = lane & 3;

    // two resident Q A-fragments: rows qt*128 + wid*32 + {g,g+8} and +16
    const __half* qp = g_qh + ((size_t)(bh * N_ + qt * TJ + wid * 32)) * DH;
    u32 qa0 = *(const u32*)(qp + (size_t)g * DH + 2 * w);
    u32 qa1 = *(const u32*)(qp + (size_t)(g + 8) * DH + 2 * w);
    u32 qa2 = *(const u32*)(qp + (size_t)g * DH + 2 * w + 8);
    u32 qa3 = *(const u32*)(qp + (size_t)(g + 8) * DH + 2 * w + 8);
    const __half* qp2 = qp + (size_t)16 * DH;
    u32 qb0 = *(const u32*)(qp2 + (size_t)g * DH + 2 * w);
    u32 qb1 = *(const u32*)(qp2 + (size_t)(g + 8) * DH + 2 * w);
    u32 qb2 = *(const u32*)(qp2 + (size_t)g * DH + 2 * w + 8);
    u32 qb3 = *(const u32*)(qp2 + (size_t)(g + 8) * DH + 2 * w + 8);

    float oA[8], oB[8];
    #pragma unroll
    for (int i = 0; i < 8; i++) { oA[i] = 0.f; oB[i] = 0.f; }
    float l0 = 0.f, l1 = 0.f, l2 = 0.f, l3 = 0.f;

    const __half hns = __float2half(NSHIFT);
    const u32 ns2 = ((u32)__half_as_ushort(hns) << 16) | __half_as_ushort(hns);

    // staging: thread -> key row tid (32B K row + 32B V row via 2+2 cp.async)
    const int ki = tid;
    const int jbase = sp * NT4 * TJ;
    const u32* kg = (const u32*)g_kh + (size_t)bh * J_ * 8;
    const u32* vg = (const u32*)g_vh + (size_t)bh * J_ * 8;

    const u32 sKa = smem_u32(sK), sVa = smem_u32(sV);
    const u32 kdst = sKa + (u32)(ki * 48);
    const u32 vdst = sVa + (u32)(ki * 48);

    // ldmatrix lane addresses (buffer 0 base)
    const int r8 = lane & 7, m4 = lane >> 3;
    const u32 kaddr0 = sKa + (u32)((((m4 >> 1) * 8 + r8) * 48) + (m4 & 1) * 16);
    const u32 vaddr0 = sVa + (u32)((((m4 & 1) * 8 + r8) * 48) + (m4 >> 1) * 16);

    #define ISSUE(buf, tile) do {                                                   \
        size_t jrow = (size_t)(jbase + (tile) * TJ + ki) * 8;                        \
        asm volatile("cp.async.ca.shared.global [%0], [%1], 16;"                    \
                     :: "r"(kdst + (buf) * BUFB), "l"(kg + jrow));                   \
        asm volatile("cp.async.ca.shared.global [%0], [%1], 16;"                    \
                     :: "r"(kdst + (buf) * BUFB + 16), "l"(kg + jrow + 4));          \
        asm volatile("cp.async.ca.shared.global [%0], [%1], 16;"                    \
                     :: "r"(vdst + (buf) * BUFB), "l"(vg + jrow));                   \
        asm volatile("cp.async.ca.shared.global [%0], [%1], 16;"                    \
                     :: "r"(vdst + (buf) * BUFB + 16), "l"(vg + jrow + 4));          \
        asm volatile("cp.async.commit_group;");                                     \
    } while (0)

    ISSUE(0, 0);
    ISSUE(1, 1);

    int bufc = 0;
    for (int t = 0; t < NT4; t++) {
        if (t + 1 < NT4) {
            asm volatile("cp.async.wait_group 1;");
        } else {
            asm volatile("cp.async.wait_group 0;");
        }
        __syncthreads();   // tile t visible; all warps done with tile t-1
        if (t + 2 < NT4) {
            int bslot = bufc + 2; if (bslot >= 3) bslot -= 3;
            ISSUE(bslot, t + 2);
        }

        const u32 kB = kaddr0 + bufc * BUFB;
        const u32 vB = vaddr0 + bufc * BUFB;
        #pragma unroll
        for (int kc = 0; kc < 8; kc++) {
            u32 kb0, kb1, kb2, kb3;
            asm volatile("ldmatrix.sync.aligned.m8n8.x4.shared.b16 {%0,%1,%2,%3}, [%4];"
                : "=r"(kb0), "=r"(kb1), "=r"(kb2), "=r"(kb3) : "r"(kB + kc * 768));
            u32 pA0, pA1, pA2, pA3, pB0, pB1, pB2, pB3;
            asm volatile("mma.sync.aligned.m16n8k16.row.col.f16.f16.f16.f16 "
                "{%0,%1}, {%2,%3,%4,%5}, {%6,%7}, {%8,%9};"
                : "=r"(pA0), "=r"(pA1)
                : "r"(qa0), "r"(qa1), "r"(qa2), "r"(qa3), "r"(kb0), "r"(kb1),
                  "r"(ns2), "r"(ns2));
            asm volatile("mma.sync.aligned.m16n8k16.row.col.f16.f16.f16.f16 "
                "{%0,%1}, {%2,%3,%4,%5}, {%6,%7}, {%8,%9};"
                : "=r"(pA2), "=r"(pA3)
                : "r"(qa0), "r"(qa1), "r"(qa2), "r"(qa3), "r"(kb2), "r"(kb3),
                  "r"(ns2), "r"(ns2));
            asm volatile("mma.sync.aligned.m16n8k16.row.col.f16.f16.f16.f16 "
                "{%0,%1}, {%2,%3,%4,%5}, {%6,%7}, {%8,%9};"
                : "=r"(pB0), "=r"(pB1)
                : "r"(qb0), "r"(qb1), "r"(qb2), "r"(qb3), "r"(kb0), "r"(kb1),
                  "r"(ns2), "r"(ns2));
            asm volatile("mma.sync.aligned.m16n8k16.row.col.f16.f16.f16.f16 "
                "{%0,%1}, {%2,%3,%4,%5}, {%6,%7}, {%8,%9};"
                : "=r"(pB2), "=r"(pB3)
                : "r"(qb0), "r"(qb1), "r"(qb2), "r"(qb3), "r"(kb2), "r"(kb3),
                  "r"(ns2), "r"(ns2));
            asm("ex2.approx.f16x2 %0, %0;" : "+r"(pA0));
            asm("ex2.approx.f16x2 %0, %0;" : "+r"(pA1));
            asm("ex2.approx.f16x2 %0, %0;" : "+r"(pA2));
            asm("ex2.approx.f16x2 %0, %0;" : "+r"(pA3));
            asm("ex2.approx.f16x2 %0, %0;" : "+r"(pB0));
            asm("ex2.approx.f16x2 %0, %0;" : "+r"(pB1));
            asm("ex2.approx.f16x2 %0, %0;" : "+r"(pB2));
            asm("ex2.approx.f16x2 %0, %0;" : "+r"(pB3));
            {
                __half2 tA0 = __hadd2(*(__half2*)&pA0, *(__half2*)&pA2);
                __half2 tA1 = __hadd2(*(__half2*)&pA1, *(__half2*)&pA3);
                __half2 tB0 = __hadd2(*(__half2*)&pB0, *(__half2*)&pB2);
                __half2 tB1 = __hadd2(*(__half2*)&pB1, *(__half2*)&pB3);
                float2 fA0 = __half22float2(tA0);
                float2 fA1 = __half22float2(tA1);
                float2 fB0 = __half22float2(tB0);
                float2 fB1 = __half22float2(tB1);
                l0 += fA0.x + fA0.y;
                l1 += fA1.x + fA1.y;
                l2 += fB0.x + fB0.y;
                l3 += fB1.x + fB1.y;
            }
            u32 v0, v1, v2, v3;
            asm volatile("ldmatrix.sync.aligned.m8n8.x4.trans.shared.b16 {%0,%1,%2,%3}, [%4];"
                : "=r"(v0), "=r"(v1), "=r"(v2), "=r"(v3) : "r"(vB + kc * 768));
            asm volatile("mma.sync.aligned.m16n8k16.row.col.f32.f16.f16.f32 "
                "{%0,%1,%2,%3}, {%4,%5,%6,%7}, {%8,%9}, {%0,%1,%2,%3};"
                : "+f"(oA[0]), "+f"(oA[1]), "+f"(oA[2]), "+f"(oA[3])
                : "r"(pA0), "r"(pA1), "r"(pA2), "r"(pA3), "r"(v0), "r"(v1));
            asm volatile("mma.sync.aligned.m16n8k16.row.col.f32.f16.f16.f32 "
                "{%0,%1,%2,%3}, {%4,%5,%6,%7}, {%8,%9}, {%0,%1,%2,%3};"
                : "+f"(oA[4]), "+f"(oA[5]), "+f"(oA[6]), "+f"(oA[7])
                : "r"(pA0), "r"(pA1), "r"(pA2), "r"(pA3), "r"(v2), "r"(v3));
            asm volatile("mma.sync.aligned.m16n8k16.row.col.f32.f16.f16.f32 "
                "{%0,%1,%2,%3}, {%4,%5,%6,%7}, {%8,%9}, {%0,%1,%2,%3};"
                : "+f"(oB[0]), "+f"(oB[1]), "+f"(oB[2]), "+f"(oB[3])
                : "r"(pB0), "r"(pB1), "r"(pB2), "r"(pB3), "r"(v0), "r"(v1));
            asm volatile("mma.sync.aligned.m16n8k16.row.col.f32.f16.f16.f32 "
                "{%0,%1,%2,%3}, {%4,%5,%6,%7}, {%8,%9}, {%0,%1,%2,%3};"
                : "+f"(oB[4]), "+f"(oB[5]), "+f"(oB[6]), "+f"(oB[7])
                : "r"(pB0), "r"(pB1), "r"(pB2), "r"(pB3), "r"(v2), "r"(v3));
        }
        bufc = (bufc + 1 == 3) ? 0 : bufc + 1;
    }
    #undef ISSUE

    // reduce l across the quad (keys partitioned over w=0..3)
    l0 += __shfl_xor_sync(0xffffffffu, l0, 1);
    l0 += __shfl_xor_sync(0xffffffffu, l0, 2);
    l1 += __shfl_xor_sync(0xffffffffu, l1, 1);
    l1 += __shfl_xor_sync(0xffffffffu, l1, 2);
    l2 += __shfl_xor_sync(0xffffffffu, l2, 1);
    l2 += __shfl_xor_sync(0xffffffffu, l2, 2);
    l3 += __shfl_xor_sync(0xffffffffu, l3, 1);
    l3 += __shfl_xor_sync(0xffffffffu, l3, 2);

    int row0 = qt * TJ + wid * 32 + g;
    size_t pb = ((size_t)(bh * NSPLIT + sp) * N_ + row0) * DH;
    float* o0 = g_accP + pb;                        // row0
    float* o1 = g_accP + pb + (size_t)8 * DH;       // row0+8
    float* o2 = g_accP + pb + (size_t)16 * DH;      // row0+16
    float* o3 = g_accP + pb + (size_t)24 * DH;      // row0+24
    o0[2 * w]     = oA[0]; o0[2 * w + 1]     = oA[1];
    o0[8 + 2 * w] = oA[4]; o0[8 + 2 * w + 1] = oA[5];
    o1[2 * w]     = oA[2]; o1[2 * w + 1]     = oA[3];
    o1[8 + 2 * w] = oA[6]; o1[8 + 2 * w + 1] = oA[7];
    o2[2 * w]     = oB[0]; o2[2 * w + 1]     = oB[1];
    o2[8 + 2 * w] = oB[4]; o2[8 + 2 * w + 1] = oB[5];
    o3[2 * w]     = oB[2]; o3[2 * w + 1]     = oB[3];
    o3[8 + 2 * w] = oB[6]; o3[8 + 2 * w + 1] = oB[7];
    if (w == 0) {
        size_t lb = (size_t)(bh * NSPLIT + sp) * N_ + row0;
        g_lP[lb]      = l0;
        g_lP[lb + 8]  = l1;
        g_lP[lb + 16] = l2;
        g_lP[lb + 24] = l3;
    }
}

// ---- K4: epilogue GEMM, 16-token tiles for 2x grid (256 CTAs).
//      combine + residual -> LN2 -> y @ wout^T + bias + res ----
__global__ void __launch_bounds__(256) k_epi(const float* __restrict__ x,
                      const float* __restrict__ wout,
                      const float* __restrict__ bout, const float* __restrict__ g2,
                      const float* __restrict__ b2, float* __restrict__ out) {
    __shared__ float R[16 * 132];    // shv, then sy (in-place normalize)
    __shared__ float sw[64 * 36];    // wout tile [64 out][32 k], stride 36
    __shared__ float smu[16], srv[16];
    const int tok0 = blockIdx.x * 16;
    const int oc = blockIdx.y;       // output half: cols oc*64 .. oc*64+63
    const int tid = threadIdx.x;
    const int og = tid & 31, tg = tid >> 5;

    // 1. combine splits + residual -> R (stride 132)
    for (int i = tid; i < 16 * 128; i += 256) {
        int tt = i >> 7, d = i & 127;
        int gt = tok0 + tt;
        int b = gt >> 9, t = gt & 511;
        int bh = b * H_ + (d >> 4);
        int dd = d & 15;
        float num = 0.f, l = 0.f;
        #pragma unroll
        for (int s = 0; s < NSPLIT; s++) {
            num += g_accP[((size_t)(bh * NSPLIT + s) * N_ + t) * DH + dd];
            l   += g_lP[(size_t)(bh * NSPLIT + s) * N_ + t];
        }
        R[tt * 132 + d] = __fdividef(num, l) + x[(size_t)gt * DIM + d];
    }
    __syncthreads();

    // 2. LN2 stats: 16 lanes per token (aligned 16-lane shfl groups)
    {
        int tok = tid >> 4, sub = tid & 15;
        const float* rr = R + tok * 132 + sub * 8;
        float sum = 0.f, sq = 0.f;
        #pragma unroll
        for (int i = 0; i < 2; i++) {
            float4 v = *(const float4*)(rr + i * 4);
            sum += v.x + v.y + v.z + v.w;
            sq  += v.x * v.x + v.y * v.y + v.z * v.z + v.w * v.w;
        }
        #pragma unroll
        for (int o = 8; o; o >>= 1) {
            sum += __shfl_xor_sync(~0u, sum, o);
            sq  += __shfl_xor_sync(~0u, sq, o);
        }
        float mu = sum * (1.0f / 128.0f);
        float var = sq * (1.0f / 128.0f) - mu * mu;
        if (sub == 0) { smu[tok] = mu; srv[tok] = rsqrtf(var + 1e-5f); }
    }
    __syncthreads();

    // 3. park residuals in registers, then normalize R in place
    float res[2][2];
    #pragma unroll
    for (int t = 0; t < 2; t++)
        #pragma unroll
        for (int o = 0; o < 2; o++)
            res[t][o] = R[(tg * 2 + t) * 132 + oc * 64 + og + 32 * o];
    __syncthreads();   // all residual reads complete before overwrite
    for (int i = tid; i < 16 * 128; i += 256) {
        int tt = i >> 7, d = i & 127;
        float v = R[tt * 132 + d];
        R[tt * 132 + d] = (v - smu[tt]) * srv[tt] * g2[d] + b2[d];
    }
    __syncthreads();

    // 4. GEMM: 4 k-chunks of 32
    float acc[2][2];
    #pragma unroll
    for (int t = 0; t < 2; t++) { acc[t][0] = 0.f; acc[t][1] = 0.f; }
    const float* wbase = wout + (size_t)(oc * 64) * DIM;
    for (int kc = 0; kc < 4; kc++) {
        #pragma unroll
        for (int i = 0; i < 2; i++) {
            int idx = tid + i * 256;
            int o = idx >> 3, k4 = (idx & 7) * 4;
            *(float4*)&sw[o * 36 + k4] =
                *(const float4*)&wbase[(size_t)o * DIM + kc * 32 + k4];
        }
        __syncthreads();
        const float* swb = sw + og * 36;
        const float* sxb = R + tg * 2 * 132 + kc * 32;
        #pragma unroll
        for (int ks = 0; ks < 8; ks++) {
            float4 w0 = *(const float4*)&swb[0 * 1152 + ks * 4];   // out og
            float4 w1 = *(const float4*)&swb[1 * 1152 + ks * 4];   // out og+32
            #pragma unroll
            for (int t = 0; t < 2; t++) {
                float4 xv = *(const float4*)&sxb[t * 132 + ks * 4];
                acc[t][0] += xv.x * w0.x + xv.y * w0.y + xv.z * w0.z + xv.w * w0.w;
                acc[t][1] += xv.x * w1.x + xv.y * w1.y + xv.z * w1.z + xv.w * w1.w;
            }
        }
        __syncthreads();
    }

    // 5. write out = gemm + bias + residual
    #pragma unroll
    for (int t = 0; t < 2; t++) {
        int gt = tok0 + tg * 2 + t;
        #pragma unroll
        for (int o = 0; o < 2; o++) {
            int oo = oc * 64 + og + 32 * o;
            out[(size_t)gt * DIM + oo] = acc[t][o] + bout[oo] + res[t][o];
        }
    }
}

extern "C" void kernel_launch(void* const* d_in, const int* in_sizes, int n_in,
                              void* d_out, int out_size) {
    const float* x      = (const float*)d_in[0];
    const float* mem_kv = (const float*)d_in[1];
    const float* w_q    = (const float*)d_in[2];
    const float* w_kv   = (const float*)d_in[3];
    const float* w_out  = (const float*)d_in[4];
    const float* b_out  = (const float*)d_in[5];
    const float* g1     = (const float*)d_in[6];
    const float* b1     = (const float*)d_in[7];
    const float* g2     = (const float*)d_in[8];
    const float* b2     = (const float*)d_in[9];

    float* out = (float*)d_out;                  // [4,512,128]
    float* memkv_out = out + (size_t)NTOK * DIM; // [4,8,8704,32]

    k_head<<<464, 256>>>(x, g1, b1, w_q, w_kv, memkv_out);
    k_mid<<<9728, 256>>>((const float4*)mem_kv, (float4*)memkv_out);
    k_attn<<<dim3(BH, 4, NSPLIT), 128>>>();
    k_epi<<<dim3(128, 2), 256>>>(x, w_out, b_out, g2, b2, out);
}